// round 1
// baseline (speedup 1.0000x reference)
#include <cuda_runtime.h>
#include <cstdint>

#define NN   50000
#define EE   800000
#define ET   (EE + NN)
#define DIN  512
#define DH   128
#define DC   64
#define KIT  10
#define AL   0.1f
#define OMA  0.9f

// ---------------- device scratch (static, no allocation) ----------------
__device__ int   g_deg[NN];
__device__ float g_dinv[NN];
__device__ int   g_rowptr[NN + 1];
__device__ int   g_fill[NN];
__device__ int   g_col[ET];
__device__ float g_wgt[ET];
__device__ float g_bufs[3][(size_t)NN * DH];   // 0 = h1 (h0), 1/2 = ping-pong
__device__ float g_p[2][NN];                   // scalar diffusion of ones

// ---------------- graph preprocessing ----------------
__global__ void k_init() {
    int i = blockIdx.x * blockDim.x + threadIdx.x;
    if (i < NN) { g_deg[i] = 1; g_fill[i] = 0; g_p[0][i] = 1.0f; }
}

__global__ void k_deg(const int* __restrict__ ei) {
    int e = blockIdx.x * blockDim.x + threadIdx.x;
    if (e < EE) atomicAdd(&g_deg[ei[EE + e]], 1);
}

__global__ void k_dinv() {
    int i = blockIdx.x * blockDim.x + threadIdx.x;
    if (i < NN) g_dinv[i] = rsqrtf((float)g_deg[i]);
}

// single-block exclusive scan of g_deg -> g_rowptr (50001 entries)
__global__ void k_scan() {
    __shared__ int sums[1024];
    int t = threadIdx.x;
    const int per = (NN + 1023) / 1024;   // 49
    int start = t * per;
    int end = start + per; if (end > NN) end = NN;
    int s = 0;
    for (int i = start; i < end && i >= start; i++) s += g_deg[i];
    sums[t] = s;
    __syncthreads();
    for (int off = 1; off < 1024; off <<= 1) {
        int v = (t >= off) ? sums[t - off] : 0;
        __syncthreads();
        sums[t] += v;
        __syncthreads();
    }
    int run = (t == 0) ? 0 : sums[t - 1];
    for (int i = start; i < end && i >= start; i++) { g_rowptr[i] = run; run += g_deg[i]; }
    if (end == NN && start <= NN) g_rowptr[NN] = run;
}

__global__ void k_fill(const int* __restrict__ ei) {
    int idx = blockIdx.x * blockDim.x + threadIdx.x;
    if (idx >= ET) return;
    int s, d;
    if (idx < EE) { s = ei[idx]; d = ei[EE + idx]; }
    else          { s = idx - EE; d = s; }             // self loops
    int pos = g_rowptr[d] + atomicAdd(&g_fill[d], 1);
    g_col[pos] = s;
    g_wgt[pos] = g_dinv[s] * g_dinv[d];
}

// ---------------- GEMM1: h1 = relu(x @ W1^T + b1) -> g_bufs[0] ----------------
// BM=64 (nodes) x BN=128 (all D_HID) x BK=32, 256 threads, 8x4 register tile
__global__ void __launch_bounds__(256) k_gemm1(const float* __restrict__ X,
                                               const float* __restrict__ W1,
                                               const float* __restrict__ B1) {
    __shared__ float xs[32][68];    // k-major, padded (row = 272B)
    __shared__ float ws[32][132];   // k-major, padded (row = 528B)
    int tid  = threadIdx.x;
    int brow = blockIdx.x * 64;
    int trow = tid >> 5;     // 0..7
    int tcol = tid & 31;     // 0..31
    float acc[8][4];
#pragma unroll
    for (int i = 0; i < 8; i++)
#pragma unroll
        for (int j = 0; j < 4; j++) acc[i][j] = 0.0f;

    for (int k0 = 0; k0 < DIN; k0 += 32) {
#pragma unroll
        for (int i = 0; i < 2; i++) {        // x tile: 64 rows x 8 float4
            int slot = tid + i * 256;
            int r = slot >> 3, c4 = slot & 7;
            int gr = brow + r;
            float4 v = (gr < NN) ? *(const float4*)(X + (size_t)gr * DIN + k0 + c4 * 4)
                                 : make_float4(0.f, 0.f, 0.f, 0.f);
            xs[c4 * 4 + 0][r] = v.x; xs[c4 * 4 + 1][r] = v.y;
            xs[c4 * 4 + 2][r] = v.z; xs[c4 * 4 + 3][r] = v.w;
        }
#pragma unroll
        for (int i = 0; i < 4; i++) {        // w tile: 128 rows x 8 float4
            int slot = tid + i * 256;
            int r = slot >> 3, c4 = slot & 7;
            float4 v = *(const float4*)(W1 + (size_t)r * DIN + k0 + c4 * 4);
            ws[c4 * 4 + 0][r] = v.x; ws[c4 * 4 + 1][r] = v.y;
            ws[c4 * 4 + 2][r] = v.z; ws[c4 * 4 + 3][r] = v.w;
        }
        __syncthreads();
#pragma unroll
        for (int kk = 0; kk < 32; kk++) {
            float a[8], bb[4];
#pragma unroll
            for (int i = 0; i < 8; i++) a[i] = xs[kk][trow * 8 + i];
#pragma unroll
            for (int j = 0; j < 4; j++) bb[j] = ws[kk][tcol * 4 + j];
#pragma unroll
            for (int i = 0; i < 8; i++)
#pragma unroll
                for (int j = 0; j < 4; j++) acc[i][j] += a[i] * bb[j];
        }
        __syncthreads();
    }
    int gj = tcol * 4;
    float4 bv = *(const float4*)(B1 + gj);
#pragma unroll
    for (int i = 0; i < 8; i++) {
        int gr = brow + trow * 8 + i;
        if (gr < NN) {
            float4 o;
            o.x = acc[i][0] + bv.x; o.y = acc[i][1] + bv.y;
            o.z = acc[i][2] + bv.z; o.w = acc[i][3] + bv.w;
            o.x = o.x > 0.f ? o.x : 0.f; o.y = o.y > 0.f ? o.y : 0.f;
            o.z = o.z > 0.f ? o.z : 0.f; o.w = o.w > 0.f ? o.w : 0.f;
            *(float4*)(&g_bufs[0][(size_t)gr * DH + gj]) = o;
        }
    }
}

// ---------------- APPNP diffusion on 128-dim features, warp per node ----------------
__global__ void __launch_bounds__(256) k_diff(int inb, int outb) {
    int wid  = (blockIdx.x * blockDim.x + threadIdx.x) >> 5;
    int lane = threadIdx.x & 31;
    if (wid >= NN) return;
    const float* __restrict__ xin  = g_bufs[inb];
    const float* __restrict__ h0   = g_bufs[0];
    float*       __restrict__ xout = g_bufs[outb];
    int beg = g_rowptr[wid], end = g_rowptr[wid + 1];
    float ax = 0.f, ay = 0.f, az = 0.f, aw = 0.f;
#pragma unroll 4
    for (int e = beg; e < end; e++) {
        int s = g_col[e];
        float wv = g_wgt[e];
        float4 v = *(const float4*)(xin + ((size_t)s << 7) + (lane << 2));
        ax += wv * v.x; ay += wv * v.y; az += wv * v.z; aw += wv * v.w;
    }
    float4 h = *(const float4*)(h0 + ((size_t)wid << 7) + (lane << 2));
    float4 o = make_float4(OMA * ax + AL * h.x, OMA * ay + AL * h.y,
                           OMA * az + AL * h.z, OMA * aw + AL * h.w);
    *(float4*)(xout + ((size_t)wid << 7) + (lane << 2)) = o;
}

// scalar diffusion of the ones vector (for the b2 term)
__global__ void k_pdiff(int inb, int outb) {
    int v = blockIdx.x * blockDim.x + threadIdx.x;
    if (v >= NN) return;
    const float* __restrict__ pin = g_p[inb];
    float acc = 0.f;
    int beg = g_rowptr[v], end = g_rowptr[v + 1];
#pragma unroll 4
    for (int e = beg; e < end; e++) acc += g_wgt[e] * pin[g_col[e]];
    g_p[outb][v] = OMA * acc + AL * 1.0f;   // h0 for p is the ones vector
}

// ---------------- copies ----------------
__global__ void k_copyx(const float4* __restrict__ src, float4* __restrict__ dst, int n4) {
    int i = blockIdx.x * blockDim.x + threadIdx.x;
    if (i < n4) dst[i] = src[i];
}

__global__ void k_copyemb(float* __restrict__ dst) {
    int i = blockIdx.x * blockDim.x + threadIdx.x;
    const int n4 = NN * DH / 4;
    if (i < n4) ((float4*)dst)[i] = ((const float4*)g_bufs[2])[i];
}

// ---------------- GEMM2: out = emb1 @ W2^T + p * b2^T ----------------
// block = 16 nodes x 64 cols; 256 threads, each computes 4 consecutive cols
__global__ void __launch_bounds__(256) k_gemm2(const float* __restrict__ W2,
                                               const float* __restrict__ B2,
                                               float* __restrict__ out) {
    __shared__ float wst[DH][DC + 4];   // W2 transposed [k][j], padded
    __shared__ float xs[16][DH];
    int tid = threadIdx.x;
#pragma unroll
    for (int i = 0; i < 8; i++) {       // W2: 64x128 = 2048 float4
        int slot = tid + i * 256;
        int j = slot >> 5, k4 = slot & 31;
        float4 v = *(const float4*)(W2 + (size_t)j * DH + k4 * 4);
        wst[k4 * 4 + 0][j] = v.x; wst[k4 * 4 + 1][j] = v.y;
        wst[k4 * 4 + 2][j] = v.z; wst[k4 * 4 + 3][j] = v.w;
    }
    int n0 = blockIdx.x * 16;
#pragma unroll
    for (int i = 0; i < 2; i++) {       // 16 emb rows
        int slot = tid + i * 256;
        int r = slot >> 5, k4 = slot & 31;
        int gn = n0 + r;
        float4 v = (gn < NN) ? *(const float4*)(&g_bufs[2][(size_t)gn * DH + k4 * 4])
                             : make_float4(0.f, 0.f, 0.f, 0.f);
        *(float4*)&xs[r][k4 * 4] = v;
    }
    __syncthreads();
    int nl = tid >> 4, jg = tid & 15;
    float a0 = 0.f, a1 = 0.f, a2 = 0.f, a3 = 0.f;
#pragma unroll
    for (int k = 0; k < DH; k++) {
        float xv = xs[nl][k];
        float4 wv = *(const float4*)&wst[k][jg * 4];
        a0 += xv * wv.x; a1 += xv * wv.y; a2 += xv * wv.z; a3 += xv * wv.w;
    }
    int gn = n0 + nl;
    if (gn < NN) {
        float pv = g_p[0][gn];
        float4 bv = *(const float4*)(B2 + jg * 4);
        float4 o = make_float4(a0 + pv * bv.x, a1 + pv * bv.y,
                               a2 + pv * bv.z, a3 + pv * bv.w);
        *(float4*)(out + (size_t)gn * DC + jg * 4) = o;
    }
}

// ---------------- host launcher ----------------
extern "C" void kernel_launch(void* const* d_in, const int* in_sizes, int n_in,
                              void* d_out, int out_size) {
    const float* X  = (const float*)d_in[0];
    const int*   EI = (const int*)  d_in[1];
    const float* W1 = (const float*)d_in[2];
    const float* B1 = (const float*)d_in[3];
    const float* W2 = (const float*)d_in[4];
    const float* B2 = (const float*)d_in[5];
    float* out = (float*)d_out;

    // graph preprocessing (CSR with self-loops + symmetric norm)
    k_init<<<(NN + 255) / 256, 256>>>();
    k_deg <<<(EE + 255) / 256, 256>>>(EI);
    k_dinv<<<(NN + 255) / 256, 256>>>();
    k_scan<<<1, 1024>>>();
    k_fill<<<(ET + 255) / 256, 256>>>(EI);

    // h1 = relu(x @ W1^T + b1)
    k_gemm1<<<(NN + 63) / 64, 256>>>(X, W1, B1);

    // output part 0: x passthrough (independent of everything else)
    k_copyx<<<(NN * DIN / 4 + 255) / 256, 256>>>((const float4*)X, (float4*)out,
                                                 NN * DIN / 4);

    // emb1 = APPNP(h1): buf0 is h0, ping-pong 1<->2, K=10 ends in buf2
    {
        int in = 0, ob = 1;
        for (int it = 0; it < KIT; it++) {
            k_diff<<<(NN * 32 + 255) / 256, 256>>>(in, ob);
            if (it == 0) { in = 1; ob = 2; }
            else         { int t = in; in = ob; ob = t; }
        }
    }

    // p = APPNP(ones): ping-pong 0<->1, K=10 ends in g_p[0]
    {
        int in = 0, ob = 1;
        for (int it = 0; it < KIT; it++) {
            k_pdiff<<<(NN + 255) / 256, 256>>>(in, ob);
            int t = in; in = ob; ob = t;
        }
    }

    // output part 1: emb1
    k_copyemb<<<(NN * DH / 4 + 255) / 256, 256>>>(out + (size_t)NN * DIN);

    // output part 2: out = emb1 @ W2^T + p * b2^T  (APPNP linearity)
    k_gemm2<<<(NN + 15) / 16, 256>>>(W2, B2, out + (size_t)NN * (DIN + DH));
}

// round 2
// speedup vs baseline: 1.0862x; 1.0862x over previous
#include <cuda_runtime.h>
#include <cstdint>

#define NN   50000
#define EE   800000
#define ET   (EE + NN)
#define DIN  512
#define DH   128
#define DC   64
#define KIT  10
#define AL   0.1f
#define OMA  0.9f

#define NBF  ((NN + 7) / 8)        // feature-diffusion blocks (8 warps = 8 nodes each)
#define NBP  ((NN + 255) / 256)    // p-diffusion blocks
#define NSB  ((NN + 255) / 256)    // scan blocks (196)

typedef unsigned long long u64;

// ---------------- device scratch (static, no allocation) ----------------
__device__ int   g_deg[NN];
__device__ float g_dinv[NN];
__device__ int   g_rowptr[NN + 1];
__device__ int   g_fill[NN];
__device__ int2  g_cw[ET];                       // interleaved (col, weight)
__device__ int   g_bsum[256];
__device__ float g_bufs[3][(size_t)NN * DH];     // 0 = h1 (h0), 1/2 = ping-pong
__device__ float g_p[2][NN];                     // scalar diffusion of ones

// ---------------- f32x2 helpers ----------------
__device__ __forceinline__ u64 fma2(u64 a, u64 b, u64 c) {
    u64 d; asm("fma.rn.f32x2 %0, %1, %2, %3;" : "=l"(d) : "l"(a), "l"(b), "l"(c));
    return d;
}
__device__ __forceinline__ u64 dup2(float v) {
    u64 d; asm("mov.b64 %0, {%1, %1};" : "=l"(d) : "f"(v));
    return d;
}
__device__ __forceinline__ void unpack2(u64 v, float& lo, float& hi) {
    asm("mov.b64 {%0, %1}, %2;" : "=f"(lo), "=f"(hi) : "l"(v));
}

// ---------------- graph preprocessing ----------------
__global__ void k_init() {
    int i = blockIdx.x * blockDim.x + threadIdx.x;
    if (i < NN) { g_deg[i] = 1; g_fill[i] = 0; g_p[0][i] = 1.0f; }
}

__global__ void k_deg(const int* __restrict__ ei) {
    int e = blockIdx.x * blockDim.x + threadIdx.x;
    if (e < EE) atomicAdd(&g_deg[ei[EE + e]], 1);
}

__global__ void k_dinv() {
    int i = blockIdx.x * blockDim.x + threadIdx.x;
    if (i < NN) g_dinv[i] = rsqrtf((float)g_deg[i]);
}

// multi-block exclusive scan: phase 1 (per-block local exclusive scan)
__global__ void __launch_bounds__(256) k_scan1() {
    __shared__ int sh[256];
    int t = threadIdx.x;
    int i = blockIdx.x * 256 + t;
    int v = (i < NN) ? g_deg[i] : 0;
    sh[t] = v;
    __syncthreads();
#pragma unroll
    for (int off = 1; off < 256; off <<= 1) {
        int u = (t >= off) ? sh[t - off] : 0;
        __syncthreads();
        sh[t] += u;
        __syncthreads();
    }
    if (i < NN) g_rowptr[i] = sh[t] - v;           // exclusive, block-local
    if (t == 255) g_bsum[blockIdx.x] = sh[255];
}

// phase 2: scan the block sums (NSB <= 256)
__global__ void __launch_bounds__(256) k_scan2() {
    __shared__ int sh[256];
    int t = threadIdx.x;
    int v = (t < NSB) ? g_bsum[t] : 0;
    sh[t] = v;
    __syncthreads();
#pragma unroll
    for (int off = 1; off < 256; off <<= 1) {
        int u = (t >= off) ? sh[t - off] : 0;
        __syncthreads();
        sh[t] += u;
        __syncthreads();
    }
    if (t < NSB) g_bsum[t] = sh[t] - v;            // exclusive block offsets
    if (t == 0) g_rowptr[NN] = ET;                 // total is a constant
}

// phase 3: add block offsets
__global__ void __launch_bounds__(256) k_scan3() {
    int i = blockIdx.x * 256 + threadIdx.x;
    if (i < NN) g_rowptr[i] += g_bsum[blockIdx.x];
}

__global__ void k_fill(const int* __restrict__ ei) {
    int idx = blockIdx.x * blockDim.x + threadIdx.x;
    if (idx >= ET) return;
    int s, d;
    if (idx < EE) { s = ei[idx]; d = ei[EE + idx]; }
    else          { s = idx - EE; d = s; }             // self loops
    int pos = g_rowptr[d] + atomicAdd(&g_fill[d], 1);
    float w = g_dinv[s] * g_dinv[d];
    g_cw[pos] = make_int2(s, __float_as_int(w));
}

// ---------------- GEMM1: h1 = relu(x @ W1^T + b1) -> g_bufs[0] ----------------
// BM=64 x BN=128 x BK=32, 256 threads, 8x4 register tile, packed f32x2 math
__global__ void __launch_bounds__(256) k_gemm1(const float* __restrict__ X,
                                               const float* __restrict__ W1,
                                               const float* __restrict__ B1) {
    __shared__ float xs[32][68];    // k-major, padded
    __shared__ float ws[32][132];   // k-major, padded
    int tid  = threadIdx.x;
    int brow = blockIdx.x * 64;
    int trow = tid >> 5;     // 0..7  (uniform within warp)
    int tcol = tid & 31;     // 0..31
    u64 acc2[4][4];          // [row-pair][col]; pair = rows (2p, 2p+1)
#pragma unroll
    for (int p = 0; p < 4; p++)
#pragma unroll
        for (int j = 0; j < 4; j++) acc2[p][j] = 0ull;

    for (int k0 = 0; k0 < DIN; k0 += 32) {
#pragma unroll
        for (int i = 0; i < 2; i++) {        // x tile: 64 rows x 8 float4
            int slot = tid + i * 256;
            int r = slot >> 3, c4 = slot & 7;
            int gr = brow + r;
            float4 v = (gr < NN) ? *(const float4*)(X + (size_t)gr * DIN + k0 + c4 * 4)
                                 : make_float4(0.f, 0.f, 0.f, 0.f);
            xs[c4 * 4 + 0][r] = v.x; xs[c4 * 4 + 1][r] = v.y;
            xs[c4 * 4 + 2][r] = v.z; xs[c4 * 4 + 3][r] = v.w;
        }
#pragma unroll
        for (int i = 0; i < 4; i++) {        // w tile: 128 rows x 8 float4
            int slot = tid + i * 256;
            int r = slot >> 3, c4 = slot & 7;
            float4 v = *(const float4*)(W1 + (size_t)r * DIN + k0 + c4 * 4);
            ws[c4 * 4 + 0][r] = v.x; ws[c4 * 4 + 1][r] = v.y;
            ws[c4 * 4 + 2][r] = v.z; ws[c4 * 4 + 3][r] = v.w;
        }
        __syncthreads();
#pragma unroll
        for (int kk = 0; kk < 32; kk++) {
            u64 ap[4];
#pragma unroll
            for (int p = 0; p < 4; p++)      // row pairs: 8B-aligned LDS.64, broadcast
                ap[p] = *(const u64*)&xs[kk][trow * 8 + 2 * p];
            float4 bv = *(const float4*)&ws[kk][tcol * 4];
            u64 b0 = dup2(bv.x), b1 = dup2(bv.y), b2 = dup2(bv.z), b3 = dup2(bv.w);
#pragma unroll
            for (int p = 0; p < 4; p++) {
                acc2[p][0] = fma2(ap[p], b0, acc2[p][0]);
                acc2[p][1] = fma2(ap[p], b1, acc2[p][1]);
                acc2[p][2] = fma2(ap[p], b2, acc2[p][2]);
                acc2[p][3] = fma2(ap[p], b3, acc2[p][3]);
            }
        }
        __syncthreads();
    }
    int gj = tcol * 4;
    float4 bv = *(const float4*)(B1 + gj);
#pragma unroll
    for (int p = 0; p < 4; p++) {
        float lo0, hi0, lo1, hi1, lo2, hi2, lo3, hi3;
        unpack2(acc2[p][0], lo0, hi0);
        unpack2(acc2[p][1], lo1, hi1);
        unpack2(acc2[p][2], lo2, hi2);
        unpack2(acc2[p][3], lo3, hi3);
        int gr0 = brow + trow * 8 + 2 * p;
        if (gr0 < NN) {
            float4 o;
            o.x = fmaxf(lo0 + bv.x, 0.f); o.y = fmaxf(lo1 + bv.y, 0.f);
            o.z = fmaxf(lo2 + bv.z, 0.f); o.w = fmaxf(lo3 + bv.w, 0.f);
            *(float4*)(&g_bufs[0][(size_t)gr0 * DH + gj]) = o;
        }
        if (gr0 + 1 < NN) {
            float4 o;
            o.x = fmaxf(hi0 + bv.x, 0.f); o.y = fmaxf(hi1 + bv.y, 0.f);
            o.z = fmaxf(hi2 + bv.z, 0.f); o.w = fmaxf(hi3 + bv.w, 0.f);
            *(float4*)(&g_bufs[0][(size_t)(gr0 + 1) * DH + gj]) = o;
        }
    }
}

// ---------------- fused APPNP step: features (warp/node) + scalar p (tail blocks) --
__global__ void __launch_bounds__(256) k_diff(int inb, int outb, int pin_i, int pout_i,
                                              float* __restrict__ emb_out, int last) {
    if (blockIdx.x < NBF) {
        int wid  = (blockIdx.x << 3) + (threadIdx.x >> 5);
        int lane = threadIdx.x & 31;
        if (wid >= NN) return;
        const float* __restrict__ xin = g_bufs[inb];
        float* __restrict__ xout = last ? emb_out : g_bufs[outb];
        int beg = g_rowptr[wid], end = g_rowptr[wid + 1];
        float ax = 0.f, ay = 0.f, az = 0.f, aw = 0.f;
#pragma unroll 4
        for (int e = beg; e < end; e++) {
            int2 cw = g_cw[e];
            float w = __int_as_float(cw.y);
            float4 v = *(const float4*)(xin + ((size_t)cw.x << 7) + (lane << 2));
            ax += w * v.x; ay += w * v.y; az += w * v.z; aw += w * v.w;
        }
        float4 h = *(const float4*)(&g_bufs[0][((size_t)wid << 7) + (lane << 2)]);
        float4 o = make_float4(OMA * ax + AL * h.x, OMA * ay + AL * h.y,
                               OMA * az + AL * h.z, OMA * aw + AL * h.w);
        *(float4*)(xout + ((size_t)wid << 7) + (lane << 2)) = o;
    } else {
        int v = (blockIdx.x - NBF) * 256 + threadIdx.x;
        if (v >= NN) return;
        const float* __restrict__ pin = g_p[pin_i];
        float acc = 0.f;
        int beg = g_rowptr[v], end = g_rowptr[v + 1];
#pragma unroll 4
        for (int e = beg; e < end; e++) {
            int2 cw = g_cw[e];
            acc += __int_as_float(cw.y) * pin[cw.x];
        }
        g_p[pout_i][v] = OMA * acc + AL;    // h0 for p is the ones vector
    }
}

// ---------------- copies ----------------
__global__ void k_copyx(const float4* __restrict__ src, float4* __restrict__ dst, int n4) {
    int i = blockIdx.x * blockDim.x + threadIdx.x;
    if (i < n4) dst[i] = src[i];
}

// ---------------- GEMM2: out = emb1 @ W2^T + p * b2^T ----------------
__global__ void __launch_bounds__(256) k_gemm2(const float* __restrict__ EMB,
                                               const float* __restrict__ W2,
                                               const float* __restrict__ B2,
                                               float* __restrict__ out) {
    __shared__ float wst[DH][DC + 4];   // W2 transposed [k][j], padded
    __shared__ float xs[16][DH];
    int tid = threadIdx.x;
#pragma unroll
    for (int i = 0; i < 8; i++) {       // W2: 64x128 = 2048 float4
        int slot = tid + i * 256;
        int j = slot >> 5, k4 = slot & 31;
        float4 v = *(const float4*)(W2 + (size_t)j * DH + k4 * 4);
        wst[k4 * 4 + 0][j] = v.x; wst[k4 * 4 + 1][j] = v.y;
        wst[k4 * 4 + 2][j] = v.z; wst[k4 * 4 + 3][j] = v.w;
    }
    int n0 = blockIdx.x * 16;
#pragma unroll
    for (int i = 0; i < 2; i++) {       // 16 emb rows
        int slot = tid + i * 256;
        int r = slot >> 5, k4 = slot & 31;
        int gn = n0 + r;
        float4 v = (gn < NN) ? *(const float4*)(EMB + (size_t)gn * DH + k4 * 4)
                             : make_float4(0.f, 0.f, 0.f, 0.f);
        *(float4*)&xs[r][k4 * 4] = v;
    }
    __syncthreads();
    int nl = tid >> 4, jg = tid & 15;
    float a0 = 0.f, a1 = 0.f, a2 = 0.f, a3 = 0.f;
#pragma unroll
    for (int k = 0; k < DH; k++) {
        float xv = xs[nl][k];
        float4 wv = *(const float4*)&wst[k][jg * 4];
        a0 += xv * wv.x; a1 += xv * wv.y; a2 += xv * wv.z; a3 += xv * wv.w;
    }
    int gn = n0 + nl;
    if (gn < NN) {
        float pv = g_p[0][gn];
        float4 bv = *(const float4*)(B2 + jg * 4);
        float4 o = make_float4(a0 + pv * bv.x, a1 + pv * bv.y,
                               a2 + pv * bv.z, a3 + pv * bv.w);
        *(float4*)(out + (size_t)gn * DC + jg * 4) = o;
    }
}

// ---------------- host launcher ----------------
extern "C" void kernel_launch(void* const* d_in, const int* in_sizes, int n_in,
                              void* d_out, int out_size) {
    const float* X  = (const float*)d_in[0];
    const int*   EI = (const int*)  d_in[1];
    const float* W1 = (const float*)d_in[2];
    const float* B1 = (const float*)d_in[3];
    const float* W2 = (const float*)d_in[4];
    const float* B2 = (const float*)d_in[5];
    float* out = (float*)d_out;
    float* emb_out = out + (size_t)NN * DIN;
    float* cls_out = out + (size_t)NN * (DIN + DH);

    // graph preprocessing (CSR with self-loops + symmetric norm)
    k_init <<<(NN + 255) / 256, 256>>>();
    k_deg  <<<(EE + 255) / 256, 256>>>(EI);
    k_dinv <<<(NN + 255) / 256, 256>>>();
    k_scan1<<<NSB, 256>>>();
    k_scan2<<<1, 256>>>();
    k_scan3<<<NSB, 256>>>();
    k_fill <<<(ET + 255) / 256, 256>>>(EI);

    // h1 = relu(x @ W1^T + b1)
    k_gemm1<<<(NN + 63) / 64, 256>>>(X, W1, B1);

    // output part 0: x passthrough
    k_copyx<<<(NN * DIN / 4 + 255) / 256, 256>>>((const float4*)X, (float4*)out,
                                                 NN * DIN / 4);

    // fused APPNP: features (buf0 = h0, ping-pong 1<->2) + scalar p (0<->1)
    {
        int fin = 0, fob = 1;
        int pin = 0, pob = 1;
        for (int it = 0; it < KIT; it++) {
            int last = (it == KIT - 1);
            k_diff<<<NBF + NBP, 256>>>(fin, fob, pin, pob, emb_out, last);
            if (it == 0) { fin = 1; fob = 2; }
            else         { int t = fin; fin = fob; fob = t; }
            { int t = pin; pin = pob; pob = t; }
        }
        // after 10 iters: features in emb_out, p in g_p[0]
    }

    // out = emb1 @ W2^T + p * b2^T   (APPNP linearity; emb read from d_out)
    k_gemm2<<<(NN + 15) / 16, 256>>>(emb_out, W2, B2, cls_out);
}

// round 3
// speedup vs baseline: 1.3250x; 1.2198x over previous
#include <cuda_runtime.h>
#include <cuda_fp16.h>
#include <cstdint>

#define NN   50000
#define EE   800000
#define ET   (EE + NN)
#define DIN  512
#define DH   128
#define DC   64
#define KIT  10
#define AL   0.1f
#define OMA  0.9f

#define NBF  ((NN + 7) / 8)        // feature-diffusion blocks (8 warps = 8 nodes each)
#define NBP  ((NN + 255) / 256)    // p-diffusion blocks
#define NSB  ((NN + 255) / 256)    // scan blocks (196)
#define G1B  ((NN + 63) / 64)      // gemm1 blocks (782)
#define CPB  6250                  // copy blocks fused into gemm1 (4 float4/thread)

typedef unsigned long long u64;

// ---------------- device scratch (static, no allocation) ----------------
__device__ int     g_deg[NN];
__device__ float   g_dinv[NN];
__device__ int     g_rowptr[NN + 1];
__device__ int     g_fill[NN];
__device__ int2    g_cw[ET];                     // interleaved (col, weight)
__device__ int     g_bsum[256];
__device__ float   g_h0[(size_t)NN * DH];        // h1 fp32 (the alpha term)
__device__ __half2 g_hb[2][(size_t)NN * (DH/2)]; // fp16 ping-pong iterates
__device__ float   g_p[2][NN];                   // scalar diffusion of ones

// ---------------- f32x2 helpers ----------------
__device__ __forceinline__ u64 fma2(u64 a, u64 b, u64 c) {
    u64 d; asm("fma.rn.f32x2 %0, %1, %2, %3;" : "=l"(d) : "l"(a), "l"(b), "l"(c));
    return d;
}
__device__ __forceinline__ u64 dup2(float v) {
    u64 d; asm("mov.b64 %0, {%1, %1};" : "=l"(d) : "f"(v));
    return d;
}
__device__ __forceinline__ void unpack2(u64 v, float& lo, float& hi) {
    asm("mov.b64 {%0, %1}, %2;" : "=f"(lo), "=f"(hi) : "l"(v));
}
__device__ __forceinline__ unsigned h2u(__half2 h) {
    unsigned u; *reinterpret_cast<__half2*>(&u) = h; return u;
}

// ---------------- graph preprocessing ----------------
__global__ void k_init() {
    int i = blockIdx.x * blockDim.x + threadIdx.x;
    if (i < NN) { g_deg[i] = 1; g_fill[i] = 0; g_p[0][i] = 1.0f; }
}

__global__ void k_deg(const int* __restrict__ ei) {
    int e = blockIdx.x * blockDim.x + threadIdx.x;
    if (e < EE) atomicAdd(&g_deg[ei[EE + e]], 1);
}

// phase 1 local scan + dinv computation (deg is final here)
__global__ void __launch_bounds__(256) k_scan1() {
    __shared__ int sh[256];
    int t = threadIdx.x;
    int i = blockIdx.x * 256 + t;
    int v = (i < NN) ? g_deg[i] : 0;
    if (i < NN) g_dinv[i] = rsqrtf((float)v);
    sh[t] = v;
    __syncthreads();
#pragma unroll
    for (int off = 1; off < 256; off <<= 1) {
        int u = (t >= off) ? sh[t - off] : 0;
        __syncthreads();
        sh[t] += u;
        __syncthreads();
    }
    if (i < NN) g_rowptr[i] = sh[t] - v;           // exclusive, block-local
    if (t == 255) g_bsum[blockIdx.x] = sh[255];
}

// phase 2: scan the block sums (NSB <= 256)
__global__ void __launch_bounds__(256) k_scan2() {
    __shared__ int sh[256];
    int t = threadIdx.x;
    int v = (t < NSB) ? g_bsum[t] : 0;
    sh[t] = v;
    __syncthreads();
#pragma unroll
    for (int off = 1; off < 256; off <<= 1) {
        int u = (t >= off) ? sh[t - off] : 0;
        __syncthreads();
        sh[t] += u;
        __syncthreads();
    }
    if (t < NSB) g_bsum[t] = sh[t] - v;            // exclusive block offsets
    if (t == 0) g_rowptr[NN] = ET;                 // total is a constant
}

// phase 3: add block offsets
__global__ void __launch_bounds__(256) k_scan3() {
    int i = blockIdx.x * 256 + threadIdx.x;
    if (i < NN) g_rowptr[i] += g_bsum[blockIdx.x];
}

__global__ void k_fill(const int* __restrict__ ei) {
    int idx = blockIdx.x * blockDim.x + threadIdx.x;
    if (idx >= ET) return;
    int s, d;
    if (idx < EE) { s = ei[idx]; d = ei[EE + idx]; }
    else          { s = idx - EE; d = s; }             // self loops
    int pos = g_rowptr[d] + atomicAdd(&g_fill[d], 1);
    float w = g_dinv[s] * g_dinv[d];
    g_cw[pos] = make_int2(s, __float_as_int(w));
}

// ---------------- GEMM1 (+ fused x passthrough copy) ----------------
// gemm blocks: h1 = relu(x @ W1^T + b1) -> g_h0 (fp32) and g_hb[0] (fp16)
// copy blocks: d_out[0 : NN*DIN] = X
__global__ void __launch_bounds__(256) k_gemm1(const float* __restrict__ X,
                                               const float* __restrict__ W1,
                                               const float* __restrict__ B1,
                                               float* __restrict__ outx) {
    __shared__ float xs[32][68];    // k-major, padded
    __shared__ float ws[32][132];   // k-major, padded
    int tid = threadIdx.x;

    if (blockIdx.x >= G1B) {        // ---- fused copy path ----
        const float4* src = (const float4*)X;
        float4*       dst = (float4*)outx;
        const int n4 = NN * DIN / 4;           // 6.4M
        const int stride = CPB * 256;
        int base = (blockIdx.x - G1B) * 256 + tid;
#pragma unroll
        for (int r = 0; r < 4; r++) {
            int i = base + r * stride;
            if (i < n4) dst[i] = src[i];
        }
        return;
    }

    int brow = blockIdx.x * 64;
    int trow = tid >> 5;     // 0..7
    int tcol = tid & 31;     // 0..31
    u64 acc2[4][4];          // [row-pair][col]
#pragma unroll
    for (int p = 0; p < 4; p++)
#pragma unroll
        for (int j = 0; j < 4; j++) acc2[p][j] = 0ull;

    for (int k0 = 0; k0 < DIN; k0 += 32) {
#pragma unroll
        for (int i = 0; i < 2; i++) {        // x tile: 64 rows x 8 float4
            int slot = tid + i * 256;
            int r = slot >> 3, c4 = slot & 7;
            int gr = brow + r;
            float4 v = (gr < NN) ? *(const float4*)(X + (size_t)gr * DIN + k0 + c4 * 4)
                                 : make_float4(0.f, 0.f, 0.f, 0.f);
            xs[c4 * 4 + 0][r] = v.x; xs[c4 * 4 + 1][r] = v.y;
            xs[c4 * 4 + 2][r] = v.z; xs[c4 * 4 + 3][r] = v.w;
        }
#pragma unroll
        for (int i = 0; i < 4; i++) {        // w tile: 128 rows x 8 float4
            int slot = tid + i * 256;
            int r = slot >> 3, c4 = slot & 7;
            float4 v = *(const float4*)(W1 + (size_t)r * DIN + k0 + c4 * 4);
            ws[c4 * 4 + 0][r] = v.x; ws[c4 * 4 + 1][r] = v.y;
            ws[c4 * 4 + 2][r] = v.z; ws[c4 * 4 + 3][r] = v.w;
        }
        __syncthreads();
#pragma unroll
        for (int kk = 0; kk < 32; kk++) {
            u64 ap[4];
#pragma unroll
            for (int p = 0; p < 4; p++)
                ap[p] = *(const u64*)&xs[kk][trow * 8 + 2 * p];
            float4 bv = *(const float4*)&ws[kk][tcol * 4];
            u64 b0 = dup2(bv.x), b1 = dup2(bv.y), b2 = dup2(bv.z), b3 = dup2(bv.w);
#pragma unroll
            for (int p = 0; p < 4; p++) {
                acc2[p][0] = fma2(ap[p], b0, acc2[p][0]);
                acc2[p][1] = fma2(ap[p], b1, acc2[p][1]);
                acc2[p][2] = fma2(ap[p], b2, acc2[p][2]);
                acc2[p][3] = fma2(ap[p], b3, acc2[p][3]);
            }
        }
        __syncthreads();
    }
    int gj = tcol * 4;
    float4 bv = *(const float4*)(B1 + gj);
#pragma unroll
    for (int p = 0; p < 4; p++) {
        float lo0, hi0, lo1, hi1, lo2, hi2, lo3, hi3;
        unpack2(acc2[p][0], lo0, hi0);
        unpack2(acc2[p][1], lo1, hi1);
        unpack2(acc2[p][2], lo2, hi2);
        unpack2(acc2[p][3], lo3, hi3);
        int gr0 = brow + trow * 8 + 2 * p;
#pragma unroll
        for (int h = 0; h < 2; h++) {
            int gr = gr0 + h;
            if (gr >= NN) continue;
            float4 o;
            if (h == 0) {
                o = make_float4(fmaxf(lo0 + bv.x, 0.f), fmaxf(lo1 + bv.y, 0.f),
                                fmaxf(lo2 + bv.z, 0.f), fmaxf(lo3 + bv.w, 0.f));
            } else {
                o = make_float4(fmaxf(hi0 + bv.x, 0.f), fmaxf(hi1 + bv.y, 0.f),
                                fmaxf(hi2 + bv.z, 0.f), fmaxf(hi3 + bv.w, 0.f));
            }
            *(float4*)(&g_h0[(size_t)gr * DH + gj]) = o;
            uint2 hp;
            hp.x = h2u(__floats2half2_rn(o.x, o.y));
            hp.y = h2u(__floats2half2_rn(o.z, o.w));
            *(uint2*)(&g_hb[0][((size_t)gr << 6) + (gj >> 1)]) = hp;
        }
    }
}

// ---------------- fused APPNP step: fp16 features (warp/node) + fp32 scalar p ----
__global__ void __launch_bounds__(256) k_diff(int inb, int outb, int pin_i, int pout_i,
                                              float* __restrict__ emb_out, int last) {
    if (blockIdx.x < NBF) {
        int wid  = (blockIdx.x << 3) + (threadIdx.x >> 5);
        int lane = threadIdx.x & 31;
        if (wid >= NN) return;
        const __half2* __restrict__ xin = g_hb[inb];
        int beg = g_rowptr[wid], end = g_rowptr[wid + 1];
        float a0 = 0.f, a1 = 0.f, a2 = 0.f, a3 = 0.f;
#pragma unroll 4
        for (int e = beg; e < end; e++) {
            int2 cw = g_cw[e];
            float w = __int_as_float(cw.y);
            uint2 raw = *(const uint2*)(xin + ((size_t)cw.x << 6) + (lane << 1));
            float2 f01 = __half22float2(*reinterpret_cast<__half2*>(&raw.x));
            float2 f23 = __half22float2(*reinterpret_cast<__half2*>(&raw.y));
            a0 += w * f01.x; a1 += w * f01.y; a2 += w * f23.x; a3 += w * f23.y;
        }
        float4 h = *(const float4*)(&g_h0[((size_t)wid << 7) + (lane << 2)]);
        float4 o = make_float4(OMA * a0 + AL * h.x, OMA * a1 + AL * h.y,
                               OMA * a2 + AL * h.z, OMA * a3 + AL * h.w);
        if (last) {
            *(float4*)(emb_out + ((size_t)wid << 7) + (lane << 2)) = o;
        } else {
            uint2 hp;
            hp.x = h2u(__floats2half2_rn(o.x, o.y));
            hp.y = h2u(__floats2half2_rn(o.z, o.w));
            *(uint2*)(&g_hb[outb][((size_t)wid << 6) + (lane << 1)]) = hp;
        }
    } else {
        int v = (blockIdx.x - NBF) * 256 + threadIdx.x;
        if (v >= NN) return;
        const float* __restrict__ pin = g_p[pin_i];
        float acc = 0.f;
        int beg = g_rowptr[v], end = g_rowptr[v + 1];
#pragma unroll 4
        for (int e = beg; e < end; e++) {
            int2 cw = g_cw[e];
            acc += __int_as_float(cw.y) * pin[cw.x];
        }
        g_p[pout_i][v] = OMA * acc + AL;    // h0 for p is the ones vector
    }
}

// ---------------- GEMM2: out = emb1 @ W2^T + p * b2^T ----------------
__global__ void __launch_bounds__(256) k_gemm2(const float* __restrict__ EMB,
                                               const float* __restrict__ W2,
                                               const float* __restrict__ B2,
                                               float* __restrict__ out) {
    __shared__ float wst[DH][DC + 4];   // W2 transposed [k][j], padded
    __shared__ float xs[16][DH];
    int tid = threadIdx.x;
#pragma unroll
    for (int i = 0; i < 8; i++) {       // W2: 64x128 = 2048 float4
        int slot = tid + i * 256;
        int j = slot >> 5, k4 = slot & 31;
        float4 v = *(const float4*)(W2 + (size_t)j * DH + k4 * 4);
        wst[k4 * 4 + 0][j] = v.x; wst[k4 * 4 + 1][j] = v.y;
        wst[k4 * 4 + 2][j] = v.z; wst[k4 * 4 + 3][j] = v.w;
    }
    int n0 = blockIdx.x * 16;
#pragma unroll
    for (int i = 0; i < 2; i++) {       // 16 emb rows
        int slot = tid + i * 256;
        int r = slot >> 5, k4 = slot & 31;
        int gn = n0 + r;
        float4 v = (gn < NN) ? *(const float4*)(EMB + (size_t)gn * DH + k4 * 4)
                             : make_float4(0.f, 0.f, 0.f, 0.f);
        *(float4*)&xs[r][k4 * 4] = v;
    }
    __syncthreads();
    int nl = tid >> 4, jg = tid & 15;
    float a0 = 0.f, a1 = 0.f, a2 = 0.f, a3 = 0.f;
#pragma unroll
    for (int k = 0; k < DH; k++) {
        float xv = xs[nl][k];
        float4 wv = *(const float4*)&wst[k][jg * 4];
        a0 += xv * wv.x; a1 += xv * wv.y; a2 += xv * wv.z; a3 += xv * wv.w;
    }
    int gn = n0 + nl;
    if (gn < NN) {
        float pv = g_p[0][gn];
        float4 bv = *(const float4*)(B2 + jg * 4);
        float4 o = make_float4(a0 + pv * bv.x, a1 + pv * bv.y,
                               a2 + pv * bv.z, a3 + pv * bv.w);
        *(float4*)(out + (size_t)gn * DC + jg * 4) = o;
    }
}

// ---------------- host launcher ----------------
extern "C" void kernel_launch(void* const* d_in, const int* in_sizes, int n_in,
                              void* d_out, int out_size) {
    const float* X  = (const float*)d_in[0];
    const int*   EI = (const int*)  d_in[1];
    const float* W1 = (const float*)d_in[2];
    const float* B1 = (const float*)d_in[3];
    const float* W2 = (const float*)d_in[4];
    const float* B2 = (const float*)d_in[5];
    float* out = (float*)d_out;
    float* emb_out = out + (size_t)NN * DIN;
    float* cls_out = out + (size_t)NN * (DIN + DH);

    // preprocessing + gemm1 ordered so the profiler slot (4th launch) = k_gemm1
    k_init <<<(NN + 255) / 256, 256>>>();
    k_deg  <<<(EE + 255) / 256, 256>>>(EI);
    k_scan1<<<NSB, 256>>>();
    k_gemm1<<<G1B + CPB, 256>>>(X, W1, B1, out);   // gemm + fused x passthrough
    k_scan2<<<1, 256>>>();
    k_scan3<<<NSB, 256>>>();
    k_fill <<<(ET + 255) / 256, 256>>>(EI);

    // fused APPNP: fp16 features (hb0 = h1, ping-pong) + fp32 scalar p
    {
        int pin = 0, pob = 1;
        for (int it = 0; it < KIT; it++) {
            int last = (it == KIT - 1);
            k_diff<<<NBF + NBP, 256>>>(it & 1, (it + 1) & 1, pin, pob, emb_out, last);
            int t = pin; pin = pob; pob = t;
        }
        // features in emb_out (fp32), p in g_p[0]
    }

    // out = emb1 @ W2^T + p * b2^T   (APPNP linearity; emb read from d_out)
    k_gemm2<<<(NN + 15) / 16, 256>>>(emb_out, W2, B2, cls_out);
}

// round 4
// speedup vs baseline: 1.3415x; 1.0125x over previous
#include <cuda_runtime.h>
#include <cuda_fp16.h>
#include <cstdint>

#define NN   50000
#define EE   800000
#define ET   (EE + NN)
#define DIN  512
#define DH   128
#define DC   64
#define KIT  10
#define AL   0.1f
#define OMA  0.9f

#define NBF  ((NN + 7) / 8)        // feature-diffusion blocks (8 warps = 8 nodes each)
#define NBP  ((NN + 255) / 256)    // p-diffusion blocks
#define NSB  ((NN + 255) / 256)    // scan blocks (196)
#define G1B  ((NN + 127) / 128)    // gemm1 blocks (391)
#define CPB  6250                  // copy blocks fused into gemm1 (4 float4/thread)

typedef unsigned long long u64;

// ---------------- device scratch (static, no allocation) ----------------
__device__ int     g_deg[NN];
__device__ float   g_dinv[NN];
__device__ int     g_rowptr[NN + 1];
__device__ int     g_fill[NN];
__device__ __align__(16) int2 g_cw[ET];          // interleaved (col, weight)
__device__ int     g_bsum[256];
__device__ float   g_h0[(size_t)NN * DH];        // h1 fp32 (the alpha term)
__device__ __half2 g_hb[2][(size_t)NN * (DH/2)]; // fp16 ping-pong iterates
__device__ float   g_p[2][NN];                   // scalar diffusion of ones

// ---------------- f32x2 helpers ----------------
__device__ __forceinline__ u64 fma2(u64 a, u64 b, u64 c) {
    u64 d; asm("fma.rn.f32x2 %0, %1, %2, %3;" : "=l"(d) : "l"(a), "l"(b), "l"(c));
    return d;
}
__device__ __forceinline__ u64 dup2(float v) {
    u64 d; asm("mov.b64 %0, {%1, %1};" : "=l"(d) : "f"(v));
    return d;
}
__device__ __forceinline__ void unpack2(u64 v, float& lo, float& hi) {
    asm("mov.b64 {%0, %1}, %2;" : "=f"(lo), "=f"(hi) : "l"(v));
}
__device__ __forceinline__ unsigned h2u(__half2 h) {
    unsigned u; *reinterpret_cast<__half2*>(&u) = h; return u;
}

// ---------------- graph preprocessing ----------------
__global__ void k_init() {
    int i = blockIdx.x * blockDim.x + threadIdx.x;
    if (i < NN) { g_deg[i] = 1; g_fill[i] = 0; g_p[0][i] = 1.0f; }
}

__global__ void k_deg(const int* __restrict__ ei) {
    int e = blockIdx.x * blockDim.x + threadIdx.x;
    if (e < EE) atomicAdd(&g_deg[ei[EE + e]], 1);
}

// phase 1 local scan + dinv (deg is final here)
__global__ void __launch_bounds__(256) k_scan1() {
    __shared__ int sh[256];
    int t = threadIdx.x;
    int i = blockIdx.x * 256 + t;
    int v = (i < NN) ? g_deg[i] : 0;
    if (i < NN) g_dinv[i] = rsqrtf((float)v);
    sh[t] = v;
    __syncthreads();
#pragma unroll
    for (int off = 1; off < 256; off <<= 1) {
        int u = (t >= off) ? sh[t - off] : 0;
        __syncthreads();
        sh[t] += u;
        __syncthreads();
    }
    if (i < NN) g_rowptr[i] = sh[t] - v;
    if (t == 255) g_bsum[blockIdx.x] = sh[255];
}

__global__ void __launch_bounds__(256) k_scan2() {
    __shared__ int sh[256];
    int t = threadIdx.x;
    int v = (t < NSB) ? g_bsum[t] : 0;
    sh[t] = v;
    __syncthreads();
#pragma unroll
    for (int off = 1; off < 256; off <<= 1) {
        int u = (t >= off) ? sh[t - off] : 0;
        __syncthreads();
        sh[t] += u;
        __syncthreads();
    }
    if (t < NSB) g_bsum[t] = sh[t] - v;
    if (t == 0) g_rowptr[NN] = ET;
}

__global__ void __launch_bounds__(256) k_scan3() {
    int i = blockIdx.x * 256 + threadIdx.x;
    if (i < NN) g_rowptr[i] += g_bsum[blockIdx.x];
}

__global__ void k_fill(const int* __restrict__ ei) {
    int idx = blockIdx.x * blockDim.x + threadIdx.x;
    if (idx >= ET) return;
    int s, d;
    if (idx < EE) { s = ei[idx]; d = ei[EE + idx]; }
    else          { s = idx - EE; d = s; }
    int pos = g_rowptr[d] + atomicAdd(&g_fill[d], 1);
    float w = g_dinv[s] * g_dinv[d];
    g_cw[pos] = make_int2(s, __float_as_int(w));
}

// ---------------- GEMM1 (+ fused x passthrough copy) ----------------
// BM=128, BN=128(all DH), BK=16, 256 threads, 8x8 thread tile, f32x2,
// software-pipelined global->reg->smem.
__global__ void __launch_bounds__(256, 2) k_gemm1(const float* __restrict__ X,
                                                  const float* __restrict__ W1,
                                                  const float* __restrict__ B1,
                                                  float* __restrict__ outx) {
    __shared__ float xs[16][132];   // k-major [kk][row]
    __shared__ float ws[16][132];   // k-major [kk][col]
    int tid = threadIdx.x;

    if (blockIdx.x >= G1B) {        // ---- fused copy path ----
        const float4* src = (const float4*)X;
        float4*       dst = (float4*)outx;
        const int n4 = NN * DIN / 4;           // 6.4M
        const int stride = CPB * 256;
        int base = (blockIdx.x - G1B) * 256 + tid;
#pragma unroll
        for (int r = 0; r < 4; r++) {
            int i = base + r * stride;
            if (i < n4) dst[i] = src[i];
        }
        return;
    }

    int brow = blockIdx.x * 128;
    int ty = tid >> 4;       // 0..15 -> rows ty*8..+8
    int tx = tid & 15;       // 0..15 -> cols tx*8..+8

    u64 acc2[4][8];          // [row-pair p][col j]: rows (ty*8+2p, +1)
#pragma unroll
    for (int p = 0; p < 4; p++)
#pragma unroll
        for (int j = 0; j < 8; j++) acc2[p][j] = 0ull;

    float4 xa[2], wa[2];
    int r0s = tid >> 2, c4s = tid & 3;       // slot 0
    int r1s = (tid + 256) >> 2;              // slot 1 (c4 same)

    auto load_stage = [&](int k0) {
        int gr0 = brow + r0s, gr1 = brow + r1s;
        xa[0] = (gr0 < NN) ? *(const float4*)(X + (size_t)gr0 * DIN + k0 + c4s * 4)
                           : make_float4(0.f, 0.f, 0.f, 0.f);
        xa[1] = (gr1 < NN) ? *(const float4*)(X + (size_t)gr1 * DIN + k0 + c4s * 4)
                           : make_float4(0.f, 0.f, 0.f, 0.f);
        wa[0] = *(const float4*)(W1 + (size_t)r0s * DIN + k0 + c4s * 4);
        wa[1] = *(const float4*)(W1 + (size_t)r1s * DIN + k0 + c4s * 4);
    };
    auto store_stage = [&]() {
        xs[c4s * 4 + 0][r0s] = xa[0].x; xs[c4s * 4 + 1][r0s] = xa[0].y;
        xs[c4s * 4 + 2][r0s] = xa[0].z; xs[c4s * 4 + 3][r0s] = xa[0].w;
        xs[c4s * 4 + 0][r1s] = xa[1].x; xs[c4s * 4 + 1][r1s] = xa[1].y;
        xs[c4s * 4 + 2][r1s] = xa[1].z; xs[c4s * 4 + 3][r1s] = xa[1].w;
        ws[c4s * 4 + 0][r0s] = wa[0].x; ws[c4s * 4 + 1][r0s] = wa[0].y;
        ws[c4s * 4 + 2][r0s] = wa[0].z; ws[c4s * 4 + 3][r0s] = wa[0].w;
        ws[c4s * 4 + 0][r1s] = wa[1].x; ws[c4s * 4 + 1][r1s] = wa[1].y;
        ws[c4s * 4 + 2][r1s] = wa[1].z; ws[c4s * 4 + 3][r1s] = wa[1].w;
    };

    load_stage(0);
    store_stage();
    __syncthreads();

    const int NSTG = DIN / 16;   // 32
    for (int s = 0; s < NSTG; s++) {
        if (s + 1 < NSTG) load_stage((s + 1) * 16);
#pragma unroll
        for (int kk = 0; kk < 16; kk++) {
            u64 ap[4];
#pragma unroll
            for (int p = 0; p < 4; p++)
                ap[p] = *(const u64*)&xs[kk][ty * 8 + 2 * p];
            float4 b0 = *(const float4*)&ws[kk][tx * 8];
            float4 b1 = *(const float4*)&ws[kk][tx * 8 + 4];
            u64 bd[8];
            bd[0] = dup2(b0.x); bd[1] = dup2(b0.y); bd[2] = dup2(b0.z); bd[3] = dup2(b0.w);
            bd[4] = dup2(b1.x); bd[5] = dup2(b1.y); bd[6] = dup2(b1.z); bd[7] = dup2(b1.w);
#pragma unroll
            for (int p = 0; p < 4; p++)
#pragma unroll
                for (int j = 0; j < 8; j++)
                    acc2[p][j] = fma2(ap[p], bd[j], acc2[p][j]);
        }
        __syncthreads();
        if (s + 1 < NSTG) {
            store_stage();
            __syncthreads();
        }
    }

    // epilogue: bias + relu, write fp32 g_h0 and fp16 g_hb[0]
    int gj = tx * 8;
    float4 bva = *(const float4*)(B1 + gj);
    float4 bvb = *(const float4*)(B1 + gj + 4);
    float bb[8] = {bva.x, bva.y, bva.z, bva.w, bvb.x, bvb.y, bvb.z, bvb.w};
#pragma unroll
    for (int p = 0; p < 4; p++) {
        float lo[8], hi[8];
#pragma unroll
        for (int j = 0; j < 8; j++) unpack2(acc2[p][j], lo[j], hi[j]);
        int r0 = brow + ty * 8 + 2 * p;
#pragma unroll
        for (int h = 0; h < 2; h++) {
            int row = r0 + h;
            if (row >= NN) continue;
            const float* sv = h ? hi : lo;
            float o[8];
#pragma unroll
            for (int j = 0; j < 8; j++) o[j] = fmaxf(sv[j] + bb[j], 0.f);
            *(float4*)(&g_h0[(size_t)row * DH + gj]) =
                make_float4(o[0], o[1], o[2], o[3]);
            *(float4*)(&g_h0[(size_t)row * DH + gj + 4]) =
                make_float4(o[4], o[5], o[6], o[7]);
            uint4 hp;
            hp.x = h2u(__floats2half2_rn(o[0], o[1]));
            hp.y = h2u(__floats2half2_rn(o[2], o[3]));
            hp.z = h2u(__floats2half2_rn(o[4], o[5]));
            hp.w = h2u(__floats2half2_rn(o[6], o[7]));
            *(uint4*)(&g_hb[0][((size_t)row << 6) + (gj >> 1)]) = hp;
        }
    }
}

// ---------------- fused APPNP step -------------------------------------------
// feature part: warp per node, batches of 8 edges (int4 edge loads + 8
// independent gathers for MLP); p part: fp32 scalar, unroll 4.
__device__ __forceinline__ void acc_edge(const __half2* __restrict__ xin,
                                         int s, float w, int lane,
                                         float& a0, float& a1, float& a2, float& a3) {
    uint2 raw = __ldg((const uint2*)(xin + ((size_t)s << 6) + (lane << 1)));
    float2 f01 = __half22float2(*reinterpret_cast<__half2*>(&raw.x));
    float2 f23 = __half22float2(*reinterpret_cast<__half2*>(&raw.y));
    a0 += w * f01.x; a1 += w * f01.y; a2 += w * f23.x; a3 += w * f23.y;
}

__global__ void __launch_bounds__(256) k_diff(int inb, int outb, int pin_i, int pout_i,
                                              float* __restrict__ emb_out, int last) {
    if (blockIdx.x < NBF) {
        int wid  = (blockIdx.x << 3) + (threadIdx.x >> 5);
        int lane = threadIdx.x & 31;
        if (wid >= NN) return;
        const __half2* __restrict__ xin = g_hb[inb];
        int beg = g_rowptr[wid], end = g_rowptr[wid + 1];
        float a0 = 0.f, a1 = 0.f, a2 = 0.f, a3 = 0.f;
        int e = beg;
        if ((e & 1) && e < end) {                 // align to 16B for int4 loads
            int2 cw = __ldg(&g_cw[e]);
            acc_edge(xin, cw.x, __int_as_float(cw.y), lane, a0, a1, a2, a3);
            e++;
        }
        for (; e + 8 <= end; e += 8) {
            int4 q0 = __ldg((const int4*)(g_cw + e));
            int4 q1 = __ldg((const int4*)(g_cw + e + 2));
            int4 q2 = __ldg((const int4*)(g_cw + e + 4));
            int4 q3 = __ldg((const int4*)(g_cw + e + 6));
            uint2 v[8];
            v[0] = __ldg((const uint2*)(xin + ((size_t)q0.x << 6) + (lane << 1)));
            v[1] = __ldg((const uint2*)(xin + ((size_t)q0.z << 6) + (lane << 1)));
            v[2] = __ldg((const uint2*)(xin + ((size_t)q1.x << 6) + (lane << 1)));
            v[3] = __ldg((const uint2*)(xin + ((size_t)q1.z << 6) + (lane << 1)));
            v[4] = __ldg((const uint2*)(xin + ((size_t)q2.x << 6) + (lane << 1)));
            v[5] = __ldg((const uint2*)(xin + ((size_t)q2.z << 6) + (lane << 1)));
            v[6] = __ldg((const uint2*)(xin + ((size_t)q3.x << 6) + (lane << 1)));
            v[7] = __ldg((const uint2*)(xin + ((size_t)q3.z << 6) + (lane << 1)));
            float wv[8] = {__int_as_float(q0.y), __int_as_float(q0.w),
                           __int_as_float(q1.y), __int_as_float(q1.w),
                           __int_as_float(q2.y), __int_as_float(q2.w),
                           __int_as_float(q3.y), __int_as_float(q3.w)};
#pragma unroll
            for (int i = 0; i < 8; i++) {
                float2 f01 = __half22float2(*reinterpret_cast<__half2*>(&v[i].x));
                float2 f23 = __half22float2(*reinterpret_cast<__half2*>(&v[i].y));
                a0 += wv[i] * f01.x; a1 += wv[i] * f01.y;
                a2 += wv[i] * f23.x; a3 += wv[i] * f23.y;
            }
        }
        for (; e + 2 <= end; e += 2) {
            int4 q = __ldg((const int4*)(g_cw + e));
            acc_edge(xin, q.x, __int_as_float(q.y), lane, a0, a1, a2, a3);
            acc_edge(xin, q.z, __int_as_float(q.w), lane, a0, a1, a2, a3);
        }
        if (e < end) {
            int2 cw = __ldg(&g_cw[e]);
            acc_edge(xin, cw.x, __int_as_float(cw.y), lane, a0, a1, a2, a3);
        }
        float4 h = *(const float4*)(&g_h0[((size_t)wid << 7) + (lane << 2)]);
        float4 o = make_float4(OMA * a0 + AL * h.x, OMA * a1 + AL * h.y,
                               OMA * a2 + AL * h.z, OMA * a3 + AL * h.w);
        if (last) {
            *(float4*)(emb_out + ((size_t)wid << 7) + (lane << 2)) = o;
        } else {
            uint2 hp;
            hp.x = h2u(__floats2half2_rn(o.x, o.y));
            hp.y = h2u(__floats2half2_rn(o.z, o.w));
            *(uint2*)(&g_hb[outb][((size_t)wid << 6) + (lane << 1)]) = hp;
        }
    } else {
        int v = (blockIdx.x - NBF) * 256 + threadIdx.x;
        if (v >= NN) return;
        const float* __restrict__ pin = g_p[pin_i];
        float acc = 0.f;
        int beg = g_rowptr[v], end = g_rowptr[v + 1];
        int e = beg;
        if ((e & 1) && e < end) {
            int2 cw = __ldg(&g_cw[e]);
            acc += __int_as_float(cw.y) * __ldg(&pin[cw.x]);
            e++;
        }
        for (; e + 4 <= end; e += 4) {
            int4 q0 = __ldg((const int4*)(g_cw + e));
            int4 q1 = __ldg((const int4*)(g_cw + e + 2));
            float p0 = __ldg(&pin[q0.x]), p1 = __ldg(&pin[q0.z]);
            float p2 = __ldg(&pin[q1.x]), p3 = __ldg(&pin[q1.z]);
            acc += __int_as_float(q0.y) * p0 + __int_as_float(q0.w) * p1
                 + __int_as_float(q1.y) * p2 + __int_as_float(q1.w) * p3;
        }
        for (; e < end; e++) {
            int2 cw = __ldg(&g_cw[e]);
            acc += __int_as_float(cw.y) * __ldg(&pin[cw.x]);
        }
        g_p[pout_i][v] = OMA * acc + AL;
    }
}

// ---------------- GEMM2: out = emb1 @ W2^T + p * b2^T ----------------
__global__ void __launch_bounds__(256) k_gemm2(const float* __restrict__ EMB,
                                               const float* __restrict__ W2,
                                               const float* __restrict__ B2,
                                               float* __restrict__ out) {
    __shared__ float wst[DH][DC + 4];
    __shared__ float xs[16][DH];
    int tid = threadIdx.x;
#pragma unroll
    for (int i = 0; i < 8; i++) {
        int slot = tid + i * 256;
        int j = slot >> 5, k4 = slot & 31;
        float4 v = *(const float4*)(W2 + (size_t)j * DH + k4 * 4);
        wst[k4 * 4 + 0][j] = v.x; wst[k4 * 4 + 1][j] = v.y;
        wst[k4 * 4 + 2][j] = v.z; wst[k4 * 4 + 3][j] = v.w;
    }
    int n0 = blockIdx.x * 16;
#pragma unroll
    for (int i = 0; i < 2; i++) {
        int slot = tid + i * 256;
        int r = slot >> 5, k4 = slot & 31;
        int gn = n0 + r;
        float4 v = (gn < NN) ? *(const float4*)(EMB + (size_t)gn * DH + k4 * 4)
                             : make_float4(0.f, 0.f, 0.f, 0.f);
        *(float4*)&xs[r][k4 * 4] = v;
    }
    __syncthreads();
    int nl = tid >> 4, jg = tid & 15;
    float a0 = 0.f, a1 = 0.f, a2 = 0.f, a3 = 0.f;
#pragma unroll
    for (int k = 0; k < DH; k++) {
        float xv = xs[nl][k];
        float4 wv = *(const float4*)&wst[k][jg * 4];
        a0 += xv * wv.x; a1 += xv * wv.y; a2 += xv * wv.z; a3 += xv * wv.w;
    }
    int gn = n0 + nl;
    if (gn < NN) {
        float pv = g_p[0][gn];
        float4 bv = *(const float4*)(B2 + jg * 4);
        float4 o = make_float4(a0 + pv * bv.x, a1 + pv * bv.y,
                               a2 + pv * bv.z, a3 + pv * bv.w);
        *(float4*)(out + (size_t)gn * DC + jg * 4) = o;
    }
}

// ---------------- host launcher ----------------
extern "C" void kernel_launch(void* const* d_in, const int* in_sizes, int n_in,
                              void* d_out, int out_size) {
    const float* X  = (const float*)d_in[0];
    const int*   EI = (const int*)  d_in[1];
    const float* W1 = (const float*)d_in[2];
    const float* B1 = (const float*)d_in[3];
    const float* W2 = (const float*)d_in[4];
    const float* B2 = (const float*)d_in[5];
    float* out = (float*)d_out;
    float* emb_out = out + (size_t)NN * DIN;
    float* cls_out = out + (size_t)NN * (DIN + DH);

    // ordered so the profiler slot (4th launch) = k_gemm1
    k_init <<<(NN + 255) / 256, 256>>>();
    k_deg  <<<(EE + 255) / 256, 256>>>(EI);
    k_scan1<<<NSB, 256>>>();
    k_gemm1<<<G1B + CPB, 256>>>(X, W1, B1, out);   // gemm + fused x passthrough
    k_scan2<<<1, 256>>>();
    k_scan3<<<NSB, 256>>>();
    k_fill <<<(ET + 255) / 256, 256>>>(EI);

    // fused APPNP: fp16 features (hb0 = h1, ping-pong) + fp32 scalar p
    {
        int pin = 0, pob = 1;
        for (int it = 0; it < KIT; it++) {
            int last = (it == KIT - 1);
            k_diff<<<NBF + NBP, 256>>>(it & 1, (it + 1) & 1, pin, pob, emb_out, last);
            int t = pin; pin = pob; pob = t;
        }
        // features in emb_out (fp32), p in g_p[0]
    }

    // out = emb1 @ W2^T + p * b2^T   (APPNP linearity; emb read from d_out)
    k_gemm2<<<(NN + 15) / 16, 256>>>(emb_out, W2, B2, cls_out);
}

// round 6
// speedup vs baseline: 1.4299x; 1.0659x over previous
#include <cuda_runtime.h>
#include <cuda_fp16.h>
#include <cuda_bf16.h>
#include <cstdint>

#define NN   50000
#define EE   800000
#define ET   (EE + NN)
#define DIN  512
#define DH   128
#define DC   64
#define KIT  10
#define AL   0.1f
#define OMA  0.9f

#define NBF2 ((NN + 63) / 64)      // feature-diffusion blocks (8 warps x 8 nodes)
#define NBP  ((NN + 255) / 256)    // p-diffusion blocks
#define NSB  ((NN + 255) / 256)    // scan blocks
#define G1B  ((NN + 127) / 128)    // gemm1 tiles (391)
#define CPB  6250                  // copy blocks fused into gemm1

typedef unsigned long long u64;

// ---------------- device scratch ----------------
__device__ int     g_deg[NN];
__device__ float   g_dinv[NN];
__device__ int     g_rowptr[NN + 1];
__device__ int     g_fill[NN];
__device__ __align__(16) int2 g_cw[ET];
__device__ int     g_bsum[256];
__device__ float   g_h0[(size_t)NN * DH];
__device__ __half2 g_hb[2][(size_t)NN * (DH/2)];
__device__ float   g_p[2][NN];

// ---------------- helpers ----------------
__device__ __forceinline__ uint32_t s2u(const void* p) {
    uint32_t a;
    asm("{ .reg .u64 t; cvta.to.shared.u64 t, %1; cvt.u32.u64 %0, t; }" : "=r"(a) : "l"(p));
    return a;
}
__device__ __forceinline__ unsigned h2u(__half2 h) {
    unsigned u; *reinterpret_cast<__half2*>(&u) = h; return u;
}
__device__ __forceinline__ unsigned b2u(__nv_bfloat162 h) {
    unsigned u; *reinterpret_cast<__nv_bfloat162*>(&u) = h; return u;
}
__device__ __forceinline__ void ldsm4(unsigned* r, uint32_t addr) {
    asm volatile("ldmatrix.sync.aligned.m8n8.x4.shared.b16 {%0,%1,%2,%3}, [%4];"
        : "=r"(r[0]), "=r"(r[1]), "=r"(r[2]), "=r"(r[3]) : "r"(addr));
}
__device__ __forceinline__ void mma16816(float* c, const unsigned* a, const unsigned* b) {
    asm volatile("mma.sync.aligned.m16n8k16.row.col.f32.bf16.bf16.f32 "
        "{%0,%1,%2,%3}, {%4,%5,%6,%7}, {%8,%9}, {%0,%1,%2,%3};"
        : "+f"(c[0]), "+f"(c[1]), "+f"(c[2]), "+f"(c[3])
        : "r"(a[0]), "r"(a[1]), "r"(a[2]), "r"(a[3]), "r"(b[0]), "r"(b[1]));
}

// ---------------- graph preprocessing ----------------
__global__ void k_init() {
    int i = blockIdx.x * blockDim.x + threadIdx.x;
    if (i < NN) { g_deg[i] = 1; g_fill[i] = 0; g_p[0][i] = 1.0f; }
}

__global__ void k_deg(const int* __restrict__ ei) {
    int e = blockIdx.x * blockDim.x + threadIdx.x;
    if (e < EE) atomicAdd(&g_deg[ei[EE + e]], 1);
}

__global__ void __launch_bounds__(256) k_scan1() {
    __shared__ int sh[256];
    int t = threadIdx.x;
    int i = blockIdx.x * 256 + t;
    int v = (i < NN) ? g_deg[i] : 0;
    if (i < NN) g_dinv[i] = rsqrtf((float)v);
    sh[t] = v;
    __syncthreads();
#pragma unroll
    for (int off = 1; off < 256; off <<= 1) {
        int u = (t >= off) ? sh[t - off] : 0;
        __syncthreads();
        sh[t] += u;
        __syncthreads();
    }
    if (i < NN) g_rowptr[i] = sh[t] - v;
    if (t == 255) g_bsum[blockIdx.x] = sh[255];
}

__global__ void __launch_bounds__(256) k_scan2() {
    __shared__ int sh[256];
    int t = threadIdx.x;
    int v = (t < NSB) ? g_bsum[t] : 0;
    sh[t] = v;
    __syncthreads();
#pragma unroll
    for (int off = 1; off < 256; off <<= 1) {
        int u = (t >= off) ? sh[t - off] : 0;
        __syncthreads();
        sh[t] += u;
        __syncthreads();
    }
    if (t < NSB) g_bsum[t] = sh[t] - v;
    if (t == 0) g_rowptr[NN] = ET;
}

__global__ void __launch_bounds__(256) k_scan3() {
    int i = blockIdx.x * 256 + threadIdx.x;
    if (i < NN) g_rowptr[i] += g_bsum[blockIdx.x];
}

__global__ void k_fill(const int* __restrict__ ei) {
    int idx = blockIdx.x * blockDim.x + threadIdx.x;
    if (idx >= ET) return;
    int s, d;
    if (idx < EE) { s = ei[idx]; d = ei[EE + idx]; }
    else          { s = idx - EE; d = s; }
    int pos = g_rowptr[d] + atomicAdd(&g_fill[d], 1);
    float w = g_dinv[s] * g_dinv[d];
    g_cw[pos] = make_int2(s, __float_as_int(w));
}

// ---------------- GEMM1 via mma.sync bf16 hi/lo split (+ fused x copy) -------
// BM=128, BN=128, BK=32; 8 warps: warp_m = wid&3 (32 rows), warp_n = wid>>2 (64 cols)
#define LDP 40   // padded smem row length (elements): 80 bytes -> 5i mod 8 swizzle
__global__ void __launch_bounds__(256, 2) k_gemm1(const float* __restrict__ X,
                                                  const float* __restrict__ W1,
                                                  const float* __restrict__ B1,
                                                  float* __restrict__ outx) {
    __shared__ __align__(16) __nv_bfloat16 sAh[128 * LDP];
    __shared__ __align__(16) __nv_bfloat16 sAl[128 * LDP];
    __shared__ __align__(16) __nv_bfloat16 sBh[128 * LDP];
    __shared__ __align__(16) __nv_bfloat16 sBl[128 * LDP];

    int tid = threadIdx.x;
    if (blockIdx.x >= G1B) {        // ---- fused copy path ----
        const float4* src = (const float4*)X;
        float4*       dst = (float4*)outx;
        const int n4 = NN * DIN / 4;
        const int stride = CPB * 256;
        int base = (blockIdx.x - G1B) * 256 + tid;
#pragma unroll
        for (int r = 0; r < 4; r++) {
            int i = base + r * stride;
            if (i < n4) dst[i] = src[i];
        }
        return;
    }

    int wid = tid >> 5, lane = tid & 31;
    int warp_m = wid & 3, warp_n = wid >> 2;
    int brow = blockIdx.x * 128;

    uint32_t uAh = s2u(sAh), uAl = s2u(sAl), uBh = s2u(sBh), uBl = s2u(sBl);

    float acc[2][8][4];
#pragma unroll
    for (int mt = 0; mt < 2; mt++)
#pragma unroll
        for (int nt = 0; nt < 8; nt++)
#pragma unroll
            for (int q = 0; q < 4; q++) acc[mt][nt][q] = 0.f;

    // per-stage load mapping: row = tid>>1 (0..127), half = (tid&1)*16 floats
    int lrow = tid >> 1;
    int lcol = (tid & 1) * 16;
    bool xok = (brow + lrow) < NN;
    const float* xrow = X  + (size_t)(brow + lrow) * DIN + lcol;
    const float* wrow = W1 + (size_t)lrow * DIN + lcol;
    uint32_t aoffh = uAh + (lrow * LDP + lcol) * 2;
    uint32_t aoffl = uAl + (lrow * LDP + lcol) * 2;
    uint32_t boffh = uBh + (lrow * LDP + lcol) * 2;
    uint32_t boffl = uBl + (lrow * LDP + lcol) * 2;

    // ldmatrix source addresses (element indices precomputed per lane)
    // A: row = warp_m*32 + mt*16 + (lane&15), col = ks + ((lane>>4)<<3)
    uint32_t a_r = warp_m * 32 + (lane & 15);
    uint32_t a_c = (lane >> 4) << 3;
    // B: row = warp_n*64 + ntp*16 + (lane&7) + ((lane>>4)<<3), col = ks + (((lane>>3)&1)<<3)
    uint32_t b_r = warp_n * 64 + (lane & 7) + ((lane >> 4) << 3);
    uint32_t b_c = ((lane >> 3) & 1) << 3;

    for (int s = 0; s < DIN / 32; s++) {
        int k0 = s * 32;
        // load + split-convert + store (X -> A, W1 -> B)
#pragma unroll
        for (int src = 0; src < 2; src++) {
            const float* gp = src ? wrow : xrow;
            bool ok = src ? true : xok;
            uint32_t oh = src ? boffh : aoffh;
            uint32_t ol = src ? boffl : aoffl;
#pragma unroll
            for (int q = 0; q < 2; q++) {      // 2 x (8 floats)
                float4 f0 = ok ? *(const float4*)(gp + k0 + q * 8)
                               : make_float4(0.f, 0.f, 0.f, 0.f);
                float4 f1 = ok ? *(const float4*)(gp + k0 + q * 8 + 4)
                               : make_float4(0.f, 0.f, 0.f, 0.f);
                __nv_bfloat162 h01 = __floats2bfloat162_rn(f0.x, f0.y);
                __nv_bfloat162 h23 = __floats2bfloat162_rn(f0.z, f0.w);
                __nv_bfloat162 h45 = __floats2bfloat162_rn(f1.x, f1.y);
                __nv_bfloat162 h67 = __floats2bfloat162_rn(f1.z, f1.w);
                float2 r01 = __bfloat1622float2(h01), r23 = __bfloat1622float2(h23);
                float2 r45 = __bfloat1622float2(h45), r67 = __bfloat1622float2(h67);
                asm volatile("st.shared.v4.b32 [%0], {%1,%2,%3,%4};"
                    :: "r"(oh + q * 16), "r"(b2u(h01)), "r"(b2u(h23)),
                       "r"(b2u(h45)), "r"(b2u(h67)) : "memory");
                asm volatile("st.shared.v4.b32 [%0], {%1,%2,%3,%4};"
                    :: "r"(ol + q * 16),
                       "r"(b2u(__floats2bfloat162_rn(f0.x - r01.x, f0.y - r01.y))),
                       "r"(b2u(__floats2bfloat162_rn(f0.z - r23.x, f0.w - r23.y))),
                       "r"(b2u(__floats2bfloat162_rn(f1.x - r45.x, f1.y - r45.y))),
                       "r"(b2u(__floats2bfloat162_rn(f1.z - r67.x, f1.w - r67.y)))
                    : "memory");
            }
        }
        __syncthreads();

#pragma unroll
        for (int ks = 0; ks < 32; ks += 16) {
            unsigned Ah[2][4], Al[2][4];
#pragma unroll
            for (int mt = 0; mt < 2; mt++) {
                uint32_t off = ((a_r + mt * 16) * LDP + ks + a_c) * 2;
                ldsm4(Ah[mt], uAh + off);
                ldsm4(Al[mt], uAl + off);
            }
#pragma unroll
            for (int ntp = 0; ntp < 4; ntp++) {
                unsigned Bh[4], Bl[4];
                uint32_t off = ((b_r + ntp * 16) * LDP + ks + b_c) * 2;
                ldsm4(Bh, uBh + off);
                ldsm4(Bl, uBl + off);
#pragma unroll
                for (int mt = 0; mt < 2; mt++) {
                    mma16816(acc[mt][ntp * 2],     Ah[mt], &Bh[0]);
                    mma16816(acc[mt][ntp * 2],     Ah[mt], &Bl[0]);
                    mma16816(acc[mt][ntp * 2],     Al[mt], &Bh[0]);
                    mma16816(acc[mt][ntp * 2 + 1], Ah[mt], &Bh[2]);
                    mma16816(acc[mt][ntp * 2 + 1], Ah[mt], &Bl[2]);
                    mma16816(acc[mt][ntp * 2 + 1], Al[mt], &Bh[2]);
                }
            }
        }
        __syncthreads();
    }

    // epilogue: bias + relu; write g_h0 (fp32) + g_hb[0] (fp16)
    int group = lane >> 2, tig = lane & 3;
#pragma unroll
    for (int mt = 0; mt < 2; mt++) {
#pragma unroll
        for (int nt = 0; nt < 8; nt++) {
            int col = warp_n * 64 + nt * 8 + 2 * tig;
            float bx = B1[col], by = B1[col + 1];
#pragma unroll
            for (int h = 0; h < 2; h++) {      // c0,c1 then c2,c3 (row, row+8)
                int row = brow + warp_m * 32 + mt * 16 + group + h * 8;
                if (row >= NN) continue;
                float v0 = fmaxf(acc[mt][nt][h * 2]     + bx, 0.f);
                float v1 = fmaxf(acc[mt][nt][h * 2 + 1] + by, 0.f);
                *(float2*)(&g_h0[(size_t)row * DH + col]) = make_float2(v0, v1);
                g_hb[0][((size_t)row << 6) + (col >> 1)] = __floats2half2_rn(v0, v1);
            }
        }
    }
}

// ---------------- fused APPNP step -------------------------------------------
__device__ __forceinline__ void acc_edge(const __half2* __restrict__ xin,
                                         int s, float w, int lane,
                                         float& a0, float& a1, float& a2, float& a3) {
    uint2 raw = __ldg((const uint2*)(xin + ((size_t)s << 6) + (lane << 1)));
    float2 f01 = __half22float2(*reinterpret_cast<__half2*>(&raw.x));
    float2 f23 = __half22float2(*reinterpret_cast<__half2*>(&raw.y));
    a0 += w * f01.x; a1 += w * f01.y; a2 += w * f23.x; a3 += w * f23.y;
}

__global__ void __launch_bounds__(256) k_diff(int inb, int outb, int pin_i, int pout_i,
                                              float* __restrict__ emb_out, int last) {
    if (blockIdx.x < NBF2) {
        // warp handles 8 consecutive nodes -> balanced (sum of 8 degrees)
        int wg   = (blockIdx.x << 3) + (threadIdx.x >> 5);
        int lane = threadIdx.x & 31;
        int n0 = wg << 3;
        int n1 = n0 + 8; if (n1 > NN) n1 = NN;
        const __half2* __restrict__ xin = g_hb[inb];
        for (int n = n0; n < n1; n++) {
            int beg = g_rowptr[n], end = g_rowptr[n + 1];
            float a0 = 0.f, a1 = 0.f, a2 = 0.f, a3 = 0.f;
            int e = beg;
            if ((e & 1) && e < end) {
                int2 cw = __ldg(&g_cw[e]);
                acc_edge(xin, cw.x, __int_as_float(cw.y), lane, a0, a1, a2, a3);
                e++;
            }
            for (; e + 8 <= end; e += 8) {
                int4 q0 = __ldg((const int4*)(g_cw + e));
                int4 q1 = __ldg((const int4*)(g_cw + e + 2));
                int4 q2 = __ldg((const int4*)(g_cw + e + 4));
                int4 q3 = __ldg((const int4*)(g_cw + e + 6));
                uint2 v[8];
                v[0] = __ldg((const uint2*)(xin + ((size_t)q0.x << 6) + (lane << 1)));
                v[1] = __ldg((const uint2*)(xin + ((size_t)q0.z << 6) + (lane << 1)));
                v[2] = __ldg((const uint2*)(xin + ((size_t)q1.x << 6) + (lane << 1)));
                v[3] = __ldg((const uint2*)(xin + ((size_t)q1.z << 6) + (lane << 1)));
                v[4] = __ldg((const uint2*)(xin + ((size_t)q2.x << 6) + (lane << 1)));
                v[5] = __ldg((const uint2*)(xin + ((size_t)q2.z << 6) + (lane << 1)));
                v[6] = __ldg((const uint2*)(xin + ((size_t)q3.x << 6) + (lane << 1)));
                v[7] = __ldg((const uint2*)(xin + ((size_t)q3.z << 6) + (lane << 1)));
                float wv[8] = {__int_as_float(q0.y), __int_as_float(q0.w),
                               __int_as_float(q1.y), __int_as_float(q1.w),
                               __int_as_float(q2.y), __int_as_float(q2.w),
                               __int_as_float(q3.y), __int_as_float(q3.w)};
#pragma unroll
                for (int i = 0; i < 8; i++) {
                    float2 f01 = __half22float2(*reinterpret_cast<__half2*>(&v[i].x));
                    float2 f23 = __half22float2(*reinterpret_cast<__half2*>(&v[i].y));
                    a0 += wv[i] * f01.x; a1 += wv[i] * f01.y;
                    a2 += wv[i] * f23.x; a3 += wv[i] * f23.y;
                }
            }
            for (; e + 2 <= end; e += 2) {
                int4 q = __ldg((const int4*)(g_cw + e));
                acc_edge(xin, q.x, __int_as_float(q.y), lane, a0, a1, a2, a3);
                acc_edge(xin, q.z, __int_as_float(q.w), lane, a0, a1, a2, a3);
            }
            if (e < end) {
                int2 cw = __ldg(&g_cw[e]);
                acc_edge(xin, cw.x, __int_as_float(cw.y), lane, a0, a1, a2, a3);
            }
            float4 h = *(const float4*)(&g_h0[((size_t)n << 7) + (lane << 2)]);
            float4 o = make_float4(OMA * a0 + AL * h.x, OMA * a1 + AL * h.y,
                                   OMA * a2 + AL * h.z, OMA * a3 + AL * h.w);
            if (last) {
                *(float4*)(emb_out + ((size_t)n << 7) + (lane << 2)) = o;
            } else {
                uint2 hp;
                hp.x = h2u(__floats2half2_rn(o.x, o.y));
                hp.y = h2u(__floats2half2_rn(o.z, o.w));
                *(uint2*)(&g_hb[outb][((size_t)n << 6) + (lane << 1)]) = hp;
            }
        }
    } else {
        int v = (blockIdx.x - NBF2) * 256 + threadIdx.x;
        if (v >= NN) return;
        const float* __restrict__ pin = g_p[pin_i];
        float acc = 0.f;
        int beg = g_rowptr[v], end = g_rowptr[v + 1];
        int e = beg;
        if ((e & 1) && e < end) {
            int2 cw = __ldg(&g_cw[e]);
            acc += __int_as_float(cw.y) * __ldg(&pin[cw.x]);
            e++;
        }
        for (; e + 4 <= end; e += 4) {
            int4 q0 = __ldg((const int4*)(g_cw + e));
            int4 q1 = __ldg((const int4*)(g_cw + e + 2));
            float p0 = __ldg(&pin[q0.x]), p1 = __ldg(&pin[q0.z]);
            float p2 = __ldg(&pin[q1.x]), p3 = __ldg(&pin[q1.z]);
            acc += __int_as_float(q0.y) * p0 + __int_as_float(q0.w) * p1
                 + __int_as_float(q1.y) * p2 + __int_as_float(q1.w) * p3;
        }
        for (; e < end; e++) {
            int2 cw = __ldg(&g_cw[e]);
            acc += __int_as_float(cw.y) * __ldg(&pin[cw.x]);
        }
        g_p[pout_i][v] = OMA * acc + AL;
    }
}

// ---------------- GEMM2: out = emb1 @ W2^T + p * b2^T ----------------
__global__ void __launch_bounds__(256) k_gemm2(const float* __restrict__ EMB,
                                               const float* __restrict__ W2,
                                               const float* __restrict__ B2,
                                               float* __restrict__ out) {
    __shared__ float wst[DH][DC + 4];
    __shared__ float xs[16][DH];
    int tid = threadIdx.x;
#pragma unroll
    for (int i = 0; i < 8; i++) {
        int slot = tid + i * 256;
        int j = slot >> 5, k4 = slot & 31;
        float4 v = *(const float4*)(W2 + (size_t)j * DH + k4 * 4);
        wst[k4 * 4 + 0][j] = v.x; wst[k4 * 4 + 1][j] = v.y;
        wst[k4 * 4 + 2][j] = v.z; wst[k4 * 4 + 3][j] = v.w;
    }
    int n0 = blockIdx.x * 16;
#pragma unroll
    for (int i = 0; i < 2; i++) {
        int slot = tid + i * 256;
        int r = slot >> 5, k4 = slot & 31;
        int gn = n0 + r;
        float4 v = (gn < NN) ? *(const float4*)(EMB + (size_t)gn * DH + k4 * 4)
                             : make_float4(0.f, 0.f, 0.f, 0.f);
        *(float4*)&xs[r][k4 * 4] = v;
    }
    __syncthreads();
    int nl = tid >> 4, jg = tid & 15;
    float a0 = 0.f, a1 = 0.f, a2 = 0.f, a3 = 0.f;
#pragma unroll
    for (int k = 0; k < DH; k++) {
        float xv = xs[nl][k];
        float4 wv = *(const float4*)&wst[k][jg * 4];
        a0 += xv * wv.x; a1 += xv * wv.y; a2 += xv * wv.z; a3 += xv * wv.w;
    }
    int gn = n0 + nl;
    if (gn < NN) {
        float pv = g_p[0][gn];
        float4 bv = *(const float4*)(B2 + jg * 4);
        float4 o = make_float4(a0 + pv * bv.x, a1 + pv * bv.y,
                               a2 + pv * bv.z, a3 + pv * bv.w);
        *(float4*)(out + (size_t)gn * DC + jg * 4) = o;
    }
}

// ---------------- host launcher ----------------
extern "C" void kernel_launch(void* const* d_in, const int* in_sizes, int n_in,
                              void* d_out, int out_size) {
    const float* X  = (const float*)d_in[0];
    const int*   EI = (const int*)  d_in[1];
    const float* W1 = (const float*)d_in[2];
    const float* B1 = (const float*)d_in[3];
    const float* W2 = (const float*)d_in[4];
    const float* B2 = (const float*)d_in[5];
    float* out = (float*)d_out;
    float* emb_out = out + (size_t)NN * DIN;
    float* cls_out = out + (size_t)NN * (DIN + DH);

    // ordered so the profiler slot (4th launch) = k_gemm1
    k_init <<<(NN + 255) / 256, 256>>>();
    k_deg  <<<(EE + 255) / 256, 256>>>(EI);
    k_scan1<<<NSB, 256>>>();
    k_gemm1<<<G1B + CPB, 256>>>(X, W1, B1, out);
    k_scan2<<<1, 256>>>();
    k_scan3<<<NSB, 256>>>();
    k_fill <<<(ET + 255) / 256, 256>>>(EI);

    // fused APPNP: fp16 features (hb0 = h1, ping-pong) + fp32 scalar p
    {
        int pin = 0, pob = 1;
        for (int it = 0; it < KIT; it++) {
            int last = (it == KIT - 1);
            k_diff<<<NBF2 + NBP, 256>>>(it & 1, (it + 1) & 1, pin, pob, emb_out, last);
            int t = pin; pin = pob; pob = t;
        }
    }

    k_gemm2<<<(NN + 15) / 16, 256>>>(emb_out, W2, B2, cls_out);
}

// round 7
// speedup vs baseline: 1.4937x; 1.0446x over previous
#include <cuda_runtime.h>
#include <cuda_fp16.h>
#include <cuda_bf16.h>
#include <cstdint>

#define NN   50000
#define EE   800000
#define ET   (EE + NN)
#define DIN  512
#define DH   128
#define DC   64
#define KIT  10
#define AL   0.1f
#define OMA  0.9f

#define NBF2 ((NN + 63) / 64)      // feature-diffusion blocks (8 warps x 8 nodes)
#define NBP  ((NN + 255) / 256)    // p-diffusion blocks
#define NSB  ((NN + 255) / 256)    // scan blocks
#define G1B  ((NN + 127) / 128)    // gemm1 tiles (391)

#define LDP    40                  // padded smem row (elements); 80B rows
#define TILE_B (128 * LDP * 2)     // bytes per smem tile (10240)
#define G1_SMEM (8 * TILE_B)       // 8 tiles (2 bufs x {Ah,Al,Bh,Bl}) = 81920

typedef unsigned long long u64;

// ---------------- device scratch ----------------
__device__ int     g_deg[NN];
__device__ float   g_dinv[NN];
__device__ int     g_rowptr[NN + 1];
__device__ int     g_fill[NN];
__device__ __align__(16) int2 g_cw[ET];
__device__ int     g_bsum[256];
__device__ __align__(16) __nv_bfloat16 g_Whi[DH * DIN];
__device__ __align__(16) __nv_bfloat16 g_Wlo[DH * DIN];
// 0/1 = ping-pong iterates, 2 = h0 (h1 after relu), all fp16
__device__ __half2 g_hb[3][(size_t)NN * (DH/2)];
__device__ float   g_p[2][NN];

// ---------------- helpers ----------------
__device__ __forceinline__ uint32_t s2u(const void* p) {
    uint32_t a;
    asm("{ .reg .u64 t; cvta.to.shared.u64 t, %1; cvt.u32.u64 %0, t; }" : "=r"(a) : "l"(p));
    return a;
}
__device__ __forceinline__ unsigned h2u(__half2 h) {
    unsigned u; *reinterpret_cast<__half2*>(&u) = h; return u;
}
__device__ __forceinline__ unsigned b2u(__nv_bfloat162 h) {
    unsigned u; *reinterpret_cast<__nv_bfloat162*>(&u) = h; return u;
}
__device__ __forceinline__ void ldsm4(unsigned* r, uint32_t addr) {
    asm volatile("ldmatrix.sync.aligned.m8n8.x4.shared.b16 {%0,%1,%2,%3}, [%4];"
        : "=r"(r[0]), "=r"(r[1]), "=r"(r[2]), "=r"(r[3]) : "r"(addr));
}
__device__ __forceinline__ void mma16816(float* c, const unsigned* a, const unsigned* b) {
    asm volatile("mma.sync.aligned.m16n8k16.row.col.f32.bf16.bf16.f32 "
        "{%0,%1,%2,%3}, {%4,%5,%6,%7}, {%8,%9}, {%0,%1,%2,%3};"
        : "+f"(c[0]), "+f"(c[1]), "+f"(c[2]), "+f"(c[3])
        : "r"(a[0]), "r"(a[1]), "r"(a[2]), "r"(a[3]), "r"(b[0]), "r"(b[1]));
}
__device__ __forceinline__ void sts128(uint32_t addr, uint4 v) {
    asm volatile("st.shared.v4.b32 [%0], {%1,%2,%3,%4};"
        :: "r"(addr), "r"(v.x), "r"(v.y), "r"(v.z), "r"(v.w) : "memory");
}

// ---------------- graph preprocessing ----------------
__global__ void k_wsplit(const float* __restrict__ W1) {
    int i = blockIdx.x * 256 + threadIdx.x;       // 256 blocks cover 65536
    float f = W1[i];
    __nv_bfloat16 h = __float2bfloat16_rn(f);
    g_Whi[i] = h;
    g_Wlo[i] = __float2bfloat16_rn(f - __bfloat162float(h));
}

__global__ void k_init() {
    int i = blockIdx.x * blockDim.x + threadIdx.x;
    if (i < NN) { g_deg[i] = 1; g_fill[i] = 0; g_p[0][i] = 1.0f; }
}

__global__ void k_deg(const int* __restrict__ ei) {
    int e = blockIdx.x * blockDim.x + threadIdx.x;
    if (e < EE) atomicAdd(&g_deg[ei[EE + e]], 1);
}

__global__ void __launch_bounds__(256) k_scan1() {
    __shared__ int sh[256];
    int t = threadIdx.x;
    int i = blockIdx.x * 256 + t;
    int v = (i < NN) ? g_deg[i] : 0;
    if (i < NN) g_dinv[i] = rsqrtf((float)v);
    sh[t] = v;
    __syncthreads();
#pragma unroll
    for (int off = 1; off < 256; off <<= 1) {
        int u = (t >= off) ? sh[t - off] : 0;
        __syncthreads();
        sh[t] += u;
        __syncthreads();
    }
    if (i < NN) g_rowptr[i] = sh[t] - v;
    if (t == 255) g_bsum[blockIdx.x] = sh[255];
}

__global__ void __launch_bounds__(256) k_scan2() {
    __shared__ int sh[256];
    int t = threadIdx.x;
    int v = (t < NSB) ? g_bsum[t] : 0;
    sh[t] = v;
    __syncthreads();
#pragma unroll
    for (int off = 1; off < 256; off <<= 1) {
        int u = (t >= off) ? sh[t - off] : 0;
        __syncthreads();
        sh[t] += u;
        __syncthreads();
    }
    if (t < NSB) g_bsum[t] = sh[t] - v;
    if (t == 0) g_rowptr[NN] = ET;
}

__global__ void __launch_bounds__(256) k_scan3() {
    int i = blockIdx.x * 256 + threadIdx.x;
    if (i < NN) g_rowptr[i] += g_bsum[blockIdx.x];
}

__global__ void k_fill(const int* __restrict__ ei) {
    int idx = blockIdx.x * blockDim.x + threadIdx.x;
    if (idx >= ET) return;
    int s, d;
    if (idx < EE) { s = ei[idx]; d = ei[EE + idx]; }
    else          { s = idx - EE; d = s; }
    int pos = g_rowptr[d] + atomicAdd(&g_fill[d], 1);
    float w = g_dinv[s] * g_dinv[d];
    g_cw[pos] = make_int2(s, __float_as_int(w));
}

// ---------------- GEMM1: double-buffered pipelined HMMA + fused x copy -------
// BM=128, BN=128, BK=32; warp_m = wid&3 (32 rows), warp_n = wid>>2 (64 cols).
// Each CTA also copies a 16384-float4 slice of X -> out (the passthrough).
__global__ void __launch_bounds__(256, 1) k_gemm1(const float* __restrict__ X,
                                                  const float* __restrict__ B1,
                                                  float* __restrict__ outx) {
    extern __shared__ __align__(16) char dsm[];
    uint32_t base = s2u(dsm);

    int tid = threadIdx.x;
    int wid = tid >> 5, lane = tid & 31;
    int warp_m = wid & 3, warp_n = wid >> 2;
    int brow = blockIdx.x * 128;

    float acc[2][8][4];
#pragma unroll
    for (int mt = 0; mt < 2; mt++)
#pragma unroll
        for (int nt = 0; nt < 8; nt++)
#pragma unroll
            for (int q = 0; q < 4; q++) acc[mt][nt][q] = 0.f;

    // stage-load mapping: row = tid>>1 (0..127), col half = (tid&1)*16
    int lrow = tid >> 1;
    int lc   = (tid & 1) * 16;
    bool xok = (brow + lrow) < NN;
    const float* xrow = X + (size_t)(brow + lrow) * DIN + lc;
    const __nv_bfloat16* whrow = g_Whi + (size_t)lrow * DIN + lc;
    const __nv_bfloat16* wlrow = g_Wlo + (size_t)lrow * DIN + lc;
    uint32_t aoff = (uint32_t)(lrow * LDP + lc) * 2;   // byte offset within tile

    // copy slice base for this CTA
    const float4* csrc = (const float4*)X;
    float4*       cdst = (float4*)outx;
    int cbase = blockIdx.x * 16384 + tid * 4;

    // ldmatrix lane addressing (element offsets within a tile)
    uint32_t a_r = warp_m * 32 + (lane & 15);
    uint32_t a_c = (lane >> 4) << 3;
    uint32_t b_r = warp_n * 64 + (lane & 7) + ((lane >> 4) << 3);
    uint32_t b_c = ((lane >> 3) & 1) << 3;

    float4 xf[4];
    uint4  whv[2], wlv[2];

    auto prefetch = [&](int s) {
        int k0 = s * 32;
        if (xok) {
            xf[0] = *(const float4*)(xrow + k0);
            xf[1] = *(const float4*)(xrow + k0 + 4);
            xf[2] = *(const float4*)(xrow + k0 + 8);
            xf[3] = *(const float4*)(xrow + k0 + 12);
        } else {
            xf[0] = xf[1] = xf[2] = xf[3] = make_float4(0.f, 0.f, 0.f, 0.f);
        }
        whv[0] = *(const uint4*)(whrow + k0);
        whv[1] = *(const uint4*)(whrow + k0 + 8);
        wlv[0] = *(const uint4*)(wlrow + k0);
        wlv[1] = *(const uint4*)(wlrow + k0 + 8);
    };
    auto cvstore = [&](int buf) {
        uint32_t tAh = base + (buf * 4 + 0) * TILE_B;
        uint32_t tAl = base + (buf * 4 + 1) * TILE_B;
        uint32_t tBh = base + (buf * 4 + 2) * TILE_B;
        uint32_t tBl = base + (buf * 4 + 3) * TILE_B;
#pragma unroll
        for (int q = 0; q < 2; q++) {
            float4 f0 = xf[q * 2], f1 = xf[q * 2 + 1];
            __nv_bfloat162 h01 = __floats2bfloat162_rn(f0.x, f0.y);
            __nv_bfloat162 h23 = __floats2bfloat162_rn(f0.z, f0.w);
            __nv_bfloat162 h45 = __floats2bfloat162_rn(f1.x, f1.y);
            __nv_bfloat162 h67 = __floats2bfloat162_rn(f1.z, f1.w);
            float2 r01 = __bfloat1622float2(h01), r23 = __bfloat1622float2(h23);
            float2 r45 = __bfloat1622float2(h45), r67 = __bfloat1622float2(h67);
            sts128(tAh + aoff + q * 16,
                   make_uint4(b2u(h01), b2u(h23), b2u(h45), b2u(h67)));
            sts128(tAl + aoff + q * 16, make_uint4(
                b2u(__floats2bfloat162_rn(f0.x - r01.x, f0.y - r01.y)),
                b2u(__floats2bfloat162_rn(f0.z - r23.x, f0.w - r23.y)),
                b2u(__floats2bfloat162_rn(f1.x - r45.x, f1.y - r45.y)),
                b2u(__floats2bfloat162_rn(f1.z - r67.x, f1.w - r67.y))));
        }
        sts128(tBh + aoff,      whv[0]);
        sts128(tBh + aoff + 16, whv[1]);
        sts128(tBl + aoff,      wlv[0]);
        sts128(tBl + aoff + 16, wlv[1]);
    };

    prefetch(0);
    cvstore(0);
    __syncthreads();

    for (int s = 0; s < DIN / 32; s++) {          // 16 stages
        if (s + 1 < DIN / 32) prefetch(s + 1);

        int buf = s & 1;
        uint32_t tAh = base + (buf * 4 + 0) * TILE_B;
        uint32_t tAl = base + (buf * 4 + 1) * TILE_B;
        uint32_t tBh = base + (buf * 4 + 2) * TILE_B;
        uint32_t tBl = base + (buf * 4 + 3) * TILE_B;
#pragma unroll
        for (int ks = 0; ks < 32; ks += 16) {
            unsigned Ah[2][4], Al[2][4];
#pragma unroll
            for (int mt = 0; mt < 2; mt++) {
                uint32_t off = ((a_r + mt * 16) * LDP + ks + a_c) * 2;
                ldsm4(Ah[mt], tAh + off);
                ldsm4(Al[mt], tAl + off);
            }
#pragma unroll
            for (int ntp = 0; ntp < 4; ntp++) {
                unsigned Bh[4], Bl[4];
                uint32_t off = ((b_r + ntp * 16) * LDP + ks + b_c) * 2;
                ldsm4(Bh, tBh + off);
                ldsm4(Bl, tBl + off);
#pragma unroll
                for (int mt = 0; mt < 2; mt++) {
                    mma16816(acc[mt][ntp * 2],     Ah[mt], &Bh[0]);
                    mma16816(acc[mt][ntp * 2],     Ah[mt], &Bl[0]);
                    mma16816(acc[mt][ntp * 2],     Al[mt], &Bh[0]);
                    mma16816(acc[mt][ntp * 2 + 1], Ah[mt], &Bh[2]);
                    mma16816(acc[mt][ntp * 2 + 1], Ah[mt], &Bl[2]);
                    mma16816(acc[mt][ntp * 2 + 1], Al[mt], &Bh[2]);
                }
            }
        }

        // fused copy chunk (independent traffic, fills MMA-wait bubbles)
        {
            int ci = cbase + s * 1024;
#pragma unroll
            for (int r = 0; r < 4; r++) {
                int i = ci + r;
                if (i < NN * DIN / 4) cdst[i] = csrc[i];
            }
        }

        if (s + 1 < DIN / 32) {
            cvstore((s + 1) & 1);
            __syncthreads();
        }
    }

    // epilogue: bias + relu; write g_hb[0] (iterate) and g_hb[2] (h0), fp16
    int group = lane >> 2, tig = lane & 3;
#pragma unroll
    for (int mt = 0; mt < 2; mt++) {
#pragma unroll
        for (int nt = 0; nt < 8; nt++) {
            int col = warp_n * 64 + nt * 8 + 2 * tig;
            float bx = B1[col], by = B1[col + 1];
#pragma unroll
            for (int h = 0; h < 2; h++) {
                int row = brow + warp_m * 32 + mt * 16 + group + h * 8;
                if (row >= NN) continue;
                float v0 = fmaxf(acc[mt][nt][h * 2]     + bx, 0.f);
                float v1 = fmaxf(acc[mt][nt][h * 2 + 1] + by, 0.f);
                __half2 hv = __floats2half2_rn(v0, v1);
                size_t off = ((size_t)row << 6) + (col >> 1);
                g_hb[0][off] = hv;
                g_hb[2][off] = hv;
            }
        }
    }
}

// ---------------- fused APPNP step -------------------------------------------
__device__ __forceinline__ void acc_edge(const __half2* __restrict__ xin,
                                         int s, float w, int lane,
                                         float& a0, float& a1, float& a2, float& a3) {
    uint2 raw = __ldg((const uint2*)(xin + ((size_t)s << 6) + (lane << 1)));
    float2 f01 = __half22float2(*reinterpret_cast<__half2*>(&raw.x));
    float2 f23 = __half22float2(*reinterpret_cast<__half2*>(&raw.y));
    a0 += w * f01.x; a1 += w * f01.y; a2 += w * f23.x; a3 += w * f23.y;
}

__global__ void __launch_bounds__(256) k_diff(int inb, int outb, int pin_i, int pout_i,
                                              float* __restrict__ emb_out, int last) {
    if (blockIdx.x < NBF2) {
        int wg   = (blockIdx.x << 3) + (threadIdx.x >> 5);
        int lane = threadIdx.x & 31;
        int n0 = wg << 3;
        int n1 = n0 + 8; if (n1 > NN) n1 = NN;
        const __half2* __restrict__ xin = g_hb[inb];
        for (int n = n0; n < n1; n++) {
            int beg = g_rowptr[n], end = g_rowptr[n + 1];
            float a0 = 0.f, a1 = 0.f, a2 = 0.f, a3 = 0.f;
            int e = beg;
            if ((e & 1) && e < end) {
                int2 cw = __ldg(&g_cw[e]);
                acc_edge(xin, cw.x, __int_as_float(cw.y), lane, a0, a1, a2, a3);
                e++;
            }
            for (; e + 8 <= end; e += 8) {
                int4 q0 = __ldg((const int4*)(g_cw + e));
                int4 q1 = __ldg((const int4*)(g_cw + e + 2));
                int4 q2 = __ldg((const int4*)(g_cw + e + 4));
                int4 q3 = __ldg((const int4*)(g_cw + e + 6));
                uint2 v[8];
                v[0] = __ldg((const uint2*)(xin + ((size_t)q0.x << 6) + (lane << 1)));
                v[1] = __ldg((const uint2*)(xin + ((size_t)q0.z << 6) + (lane << 1)));
                v[2] = __ldg((const uint2*)(xin + ((size_t)q1.x << 6) + (lane << 1)));
                v[3] = __ldg((const uint2*)(xin + ((size_t)q1.z << 6) + (lane << 1)));
                v[4] = __ldg((const uint2*)(xin + ((size_t)q2.x << 6) + (lane << 1)));
                v[5] = __ldg((const uint2*)(xin + ((size_t)q2.z << 6) + (lane << 1)));
                v[6] = __ldg((const uint2*)(xin + ((size_t)q3.x << 6) + (lane << 1)));
                v[7] = __ldg((const uint2*)(xin + ((size_t)q3.z << 6) + (lane << 1)));
                float wv[8] = {__int_as_float(q0.y), __int_as_float(q0.w),
                               __int_as_float(q1.y), __int_as_float(q1.w),
                               __int_as_float(q2.y), __int_as_float(q2.w),
                               __int_as_float(q3.y), __int_as_float(q3.w)};
#pragma unroll
                for (int i = 0; i < 8; i++) {
                    float2 f01 = __half22float2(*reinterpret_cast<__half2*>(&v[i].x));
                    float2 f23 = __half22float2(*reinterpret_cast<__half2*>(&v[i].y));
                    a0 += wv[i] * f01.x; a1 += wv[i] * f01.y;
                    a2 += wv[i] * f23.x; a3 += wv[i] * f23.y;
                }
            }
            for (; e + 2 <= end; e += 2) {
                int4 q = __ldg((const int4*)(g_cw + e));
                acc_edge(xin, q.x, __int_as_float(q.y), lane, a0, a1, a2, a3);
                acc_edge(xin, q.z, __int_as_float(q.w), lane, a0, a1, a2, a3);
            }
            if (e < end) {
                int2 cw = __ldg(&g_cw[e]);
                acc_edge(xin, cw.x, __int_as_float(cw.y), lane, a0, a1, a2, a3);
            }
            // alpha term from fp16 h0 (g_hb[2])
            uint2 hraw = __ldg((const uint2*)(g_hb[2] + ((size_t)n << 6) + (lane << 1)));
            float2 h01 = __half22float2(*reinterpret_cast<__half2*>(&hraw.x));
            float2 h23 = __half22float2(*reinterpret_cast<__half2*>(&hraw.y));
            float4 o = make_float4(OMA * a0 + AL * h01.x, OMA * a1 + AL * h01.y,
                                   OMA * a2 + AL * h23.x, OMA * a3 + AL * h23.y);
            if (last) {
                *(float4*)(emb_out + ((size_t)n << 7) + (lane << 2)) = o;
            } else {
                uint2 hp;
                hp.x = h2u(__floats2half2_rn(o.x, o.y));
                hp.y = h2u(__floats2half2_rn(o.z, o.w));
                *(uint2*)(&g_hb[outb][((size_t)n << 6) + (lane << 1)]) = hp;
            }
        }
    } else {
        int v = (blockIdx.x - NBF2) * 256 + threadIdx.x;
        if (v >= NN) return;
        const float* __restrict__ pin = g_p[pin_i];
        float acc = 0.f;
        int beg = g_rowptr[v], end = g_rowptr[v + 1];
        int e = beg;
        if ((e & 1) && e < end) {
            int2 cw = __ldg(&g_cw[e]);
            acc += __int_as_float(cw.y) * __ldg(&pin[cw.x]);
            e++;
        }
        for (; e + 4 <= end; e += 4) {
            int4 q0 = __ldg((const int4*)(g_cw + e));
            int4 q1 = __ldg((const int4*)(g_cw + e + 2));
            float p0 = __ldg(&pin[q0.x]), p1 = __ldg(&pin[q0.z]);
            float p2 = __ldg(&pin[q1.x]), p3 = __ldg(&pin[q1.z]);
            acc += __int_as_float(q0.y) * p0 + __int_as_float(q0.w) * p1
                 + __int_as_float(q1.y) * p2 + __int_as_float(q1.w) * p3;
        }
        for (; e < end; e++) {
            int2 cw = __ldg(&g_cw[e]);
            acc += __int_as_float(cw.y) * __ldg(&pin[cw.x]);
        }
        g_p[pout_i][v] = OMA * acc + AL;
    }
}

// ---------------- GEMM2: out = emb1 @ W2^T + p * b2^T ----------------
__global__ void __launch_bounds__(256) k_gemm2(const float* __restrict__ EMB,
                                               const float* __restrict__ W2,
                                               const float* __restrict__ B2,
                                               float* __restrict__ out) {
    __shared__ float wst[DH][DC + 4];
    __shared__ float xs[16][DH];
    int tid = threadIdx.x;
#pragma unroll
    for (int i = 0; i < 8; i++) {
        int slot = tid + i * 256;
        int j = slot >> 5, k4 = slot & 31;
        float4 v = *(const float4*)(W2 + (size_t)j * DH + k4 * 4);
        wst[k4 * 4 + 0][j] = v.x; wst[k4 * 4 + 1][j] = v.y;
        wst[k4 * 4 + 2][j] = v.z; wst[k4 * 4 + 3][j] = v.w;
    }
    int n0 = blockIdx.x * 16;
#pragma unroll
    for (int i = 0; i < 2; i++) {
        int slot = tid + i * 256;
        int r = slot >> 5, k4 = slot & 31;
        int gn = n0 + r;
        float4 v = (gn < NN) ? *(const float4*)(EMB + (size_t)gn * DH + k4 * 4)
                             : make_float4(0.f, 0.f, 0.f, 0.f);
        *(float4*)&xs[r][k4 * 4] = v;
    }
    __syncthreads();
    int nl = tid >> 4, jg = tid & 15;
    float a0 = 0.f, a1 = 0.f, a2 = 0.f, a3 = 0.f;
#pragma unroll
    for (int k = 0; k < DH; k++) {
        float xv = xs[nl][k];
        float4 wv = *(const float4*)&wst[k][jg * 4];
        a0 += xv * wv.x; a1 += xv * wv.y; a2 += xv * wv.z; a3 += xv * wv.w;
    }
    int gn = n0 + nl;
    if (gn < NN) {
        float pv = g_p[0][gn];
        float4 bv = *(const float4*)(B2 + jg * 4);
        float4 o = make_float4(a0 + pv * bv.x, a1 + pv * bv.y,
                               a2 + pv * bv.z, a3 + pv * bv.w);
        *(float4*)(out + (size_t)gn * DC + jg * 4) = o;
    }
}

// ---------------- host launcher ----------------
extern "C" void kernel_launch(void* const* d_in, const int* in_sizes, int n_in,
                              void* d_out, int out_size) {
    const float* X  = (const float*)d_in[0];
    const int*   EI = (const int*)  d_in[1];
    const float* W1 = (const float*)d_in[2];
    const float* B1 = (const float*)d_in[3];
    const float* W2 = (const float*)d_in[4];
    const float* B2 = (const float*)d_in[5];
    float* out = (float*)d_out;
    float* emb_out = out + (size_t)NN * DIN;
    float* cls_out = out + (size_t)NN * (DIN + DH);

    cudaFuncSetAttribute(k_gemm1, cudaFuncAttributeMaxDynamicSharedMemorySize, G1_SMEM);

    // ordered so the profiler slot (4th launch) = k_gemm1
    k_wsplit<<<256, 256>>>(W1);
    k_init  <<<(NN + 255) / 256, 256>>>();
    k_deg   <<<(EE + 255) / 256, 256>>>(EI);
    k_gemm1 <<<G1B, 256, G1_SMEM>>>(X, B1, out);   // gemm + fused x passthrough
    k_scan1 <<<NSB, 256>>>();
    k_scan2 <<<1, 256>>>();
    k_scan3 <<<NSB, 256>>>();
    k_fill  <<<(ET + 255) / 256, 256>>>(EI);

    // fused APPNP: fp16 features (hb0 = h1, ping-pong 0<->1, h0 in hb2) + p
    {
        int pin = 0, pob = 1;
        for (int it = 0; it < KIT; it++) {
            int last = (it == KIT - 1);
            k_diff<<<NBF2 + NBP, 256>>>(it & 1, (it + 1) & 1, pin, pob, emb_out, last);
            int t = pin; pin = pob; pob = t;
        }
    }

    k_gemm2<<<(NN + 15) / 16, 256>>>(emb_out, W2, B2, cls_out);
}

// round 8
// speedup vs baseline: 1.6005x; 1.0715x over previous
#include <cuda_runtime.h>
#include <cuda_fp16.h>
#include <cuda_bf16.h>
#include <cstdint>

#define NN   50000
#define EE   800000
#define ET   (EE + NN)
#define DIN  512
#define DH   128
#define DC   64
#define KIT  10
#define AL   0.1f
#define OMA  0.9f

#define NBF2 ((NN + 63) / 64)      // feature-diffusion blocks (8 warps x 8 nodes)
#define NBP  ((NN + 255) / 256)    // p-diffusion blocks
#define NSB  ((NN + 255) / 256)    // scan blocks
#define G1B  ((NN + 127) / 128)    // gemm1 tiles (391)

#define LDP    40                  // padded smem row (elements); 80B rows
#define TILE_B (128 * LDP * 2)     // bytes per smem tile (10240)
#define G1_SMEM (8 * TILE_B)       // 2 bufs x {Ah,Al,Bh,Bl} = 81920

typedef unsigned long long u64;

// ---------------- device scratch ----------------
__device__ int     g_deg[NN];
__device__ float   g_dinv[NN];
__device__ int     g_rowptr[NN + 1];
__device__ int     g_fill[NN];
__device__ __align__(16) int2 g_cw[ET];
__device__ int     g_bsum[256];
__device__ __align__(16) __nv_bfloat16 g_Whi[DH * DIN];
__device__ __align__(16) __nv_bfloat16 g_Wlo[DH * DIN];
// 0/1 = ping-pong iterates, 2 = h0 (h1 after relu), all fp16
__device__ __half2 g_hb[3][(size_t)NN * (DH/2)];
__device__ float   g_p[2][NN];

// ---------------- helpers ----------------
__device__ __forceinline__ uint32_t s2u(const void* p) {
    uint32_t a;
    asm("{ .reg .u64 t; cvta.to.shared.u64 t, %1; cvt.u32.u64 %0, t; }" : "=r"(a) : "l"(p));
    return a;
}
__device__ __forceinline__ unsigned h2u(__half2 h) {
    unsigned u; *reinterpret_cast<__half2*>(&u) = h; return u;
}
__device__ __forceinline__ unsigned b2u(__nv_bfloat162 h) {
    unsigned u; *reinterpret_cast<__nv_bfloat162*>(&u) = h; return u;
}
__device__ __forceinline__ void ldsm4(unsigned* r, uint32_t addr) {
    asm volatile("ldmatrix.sync.aligned.m8n8.x4.shared.b16 {%0,%1,%2,%3}, [%4];"
        : "=r"(r[0]), "=r"(r[1]), "=r"(r[2]), "=r"(r[3]) : "r"(addr));
}
__device__ __forceinline__ void mma16816(float* c, const unsigned* a, const unsigned* b) {
    asm volatile("mma.sync.aligned.m16n8k16.row.col.f32.bf16.bf16.f32 "
        "{%0,%1,%2,%3}, {%4,%5,%6,%7}, {%8,%9}, {%0,%1,%2,%3};"
        : "+f"(c[0]), "+f"(c[1]), "+f"(c[2]), "+f"(c[3])
        : "r"(a[0]), "r"(a[1]), "r"(a[2]), "r"(a[3]), "r"(b[0]), "r"(b[1]));
}
__device__ __forceinline__ void sts128(uint32_t addr, uint4 v) {
    asm volatile("st.shared.v4.b32 [%0], {%1,%2,%3,%4};"
        :: "r"(addr), "r"(v.x), "r"(v.y), "r"(v.z), "r"(v.w) : "memory");
}

// ---------------- preprocessing ----------------
// W1 hi/lo split (256 blocks) + per-node init (NSB extra blocks)
__global__ void k_wsplit(const float* __restrict__ W1) {
    if (blockIdx.x < 256) {
        int i = blockIdx.x * 256 + threadIdx.x;
        float f = W1[i];
        __nv_bfloat16 h = __float2bfloat16_rn(f);
        g_Whi[i] = h;
        g_Wlo[i] = __float2bfloat16_rn(f - __bfloat162float(h));
    } else {
        int i = (blockIdx.x - 256) * 256 + threadIdx.x;
        if (i < NN) { g_deg[i] = 1; g_fill[i] = 0; g_p[0][i] = 1.0f; }
    }
}

__global__ void k_deg(const int* __restrict__ ei) {
    int e = blockIdx.x * blockDim.x + threadIdx.x;
    if (e < EE) atomicAdd(&g_deg[ei[EE + e]], 1);
}

__global__ void __launch_bounds__(256) k_scan1() {
    __shared__ int sh[256];
    int t = threadIdx.x;
    int i = blockIdx.x * 256 + t;
    int v = (i < NN) ? g_deg[i] : 0;
    if (i < NN) g_dinv[i] = rsqrtf((float)v);
    sh[t] = v;
    __syncthreads();
#pragma unroll
    for (int off = 1; off < 256; off <<= 1) {
        int u = (t >= off) ? sh[t - off] : 0;
        __syncthreads();
        sh[t] += u;
        __syncthreads();
    }
    if (i < NN) g_rowptr[i] = sh[t] - v;
    if (t == 255) g_bsum[blockIdx.x] = sh[255];
}

__global__ void __launch_bounds__(256) k_scan2() {
    __shared__ int sh[256];
    int t = threadIdx.x;
    int v = (t < NSB) ? g_bsum[t] : 0;
    sh[t] = v;
    __syncthreads();
#pragma unroll
    for (int off = 1; off < 256; off <<= 1) {
        int u = (t >= off) ? sh[t - off] : 0;
        __syncthreads();
        sh[t] += u;
        __syncthreads();
    }
    if (t < NSB) g_bsum[t] = sh[t] - v;
    if (t == 0) g_rowptr[NN] = ET;
}

__global__ void __launch_bounds__(256) k_scan3() {
    int i = blockIdx.x * 256 + threadIdx.x;
    if (i < NN) g_rowptr[i] += g_bsum[blockIdx.x];
}

__global__ void k_fill(const int* __restrict__ ei) {
    int idx = blockIdx.x * blockDim.x + threadIdx.x;
    if (idx >= ET) return;
    int s, d;
    if (idx < EE) { s = ei[idx]; d = ei[EE + idx]; }
    else          { s = idx - EE; d = s; }
    int pos = g_rowptr[d] + atomicAdd(&g_fill[d], 1);
    float w = g_dinv[s] * g_dinv[d];
    g_cw[pos] = make_int2(s, __float_as_int(w));
}

// ---------------- GEMM1: 512-thread pipelined HMMA + fused x copy -----------
// BM=128, BN=128, BK=32; 16 warps, warp tile 32x32 (warp_m = wid&3, warp_n = wid>>2)
__global__ void __launch_bounds__(512, 1) k_gemm1(const float* __restrict__ X,
                                                  const float* __restrict__ B1,
                                                  float* __restrict__ outx) {
    extern __shared__ __align__(16) char dsm[];
    uint32_t base = s2u(dsm);

    int tid = threadIdx.x;
    int wid = tid >> 5, lane = tid & 31;
    int warp_m = wid & 3, warp_n = wid >> 2;   // 4 x 4 warps
    int brow = blockIdx.x * 128;

    float acc[2][4][4];        // [mt][n8 tile][quad]
#pragma unroll
    for (int mt = 0; mt < 2; mt++)
#pragma unroll
        for (int nt = 0; nt < 4; nt++)
#pragma unroll
            for (int q = 0; q < 4; q++) acc[mt][nt][q] = 0.f;

    // stage-load mapping: row = tid>>2 (0..127), col = (tid&3)*8
    int lrow = tid >> 2;
    int lc   = (tid & 3) * 8;
    bool xok = (brow + lrow) < NN;
    const float* xrow = X + (size_t)(brow + lrow) * DIN + lc;
    const __nv_bfloat16* whrow = g_Whi + (size_t)lrow * DIN + lc;
    const __nv_bfloat16* wlrow = g_Wlo + (size_t)lrow * DIN + lc;
    uint32_t aoff = (uint32_t)(lrow * LDP + lc) * 2;

    // fused x-passthrough copy
    const float4* csrc = (const float4*)X;
    float4*       cdst = (float4*)outx;

    // ldmatrix lane addressing
    uint32_t a_r = warp_m * 32 + (lane & 15);
    uint32_t a_c = (lane >> 4) << 3;
    uint32_t b_r = warp_n * 32 + (lane & 7) + ((lane >> 4) << 3);
    uint32_t b_c = ((lane >> 3) & 1) << 3;

    float4 xf[2];
    uint4  whv, wlv;

    auto prefetch = [&](int s) {
        int k0 = s * 32;
        if (xok) {
            xf[0] = *(const float4*)(xrow + k0);
            xf[1] = *(const float4*)(xrow + k0 + 4);
        } else {
            xf[0] = xf[1] = make_float4(0.f, 0.f, 0.f, 0.f);
        }
        whv = *(const uint4*)(whrow + k0);
        wlv = *(const uint4*)(wlrow + k0);
    };
    auto cvstore = [&](int buf) {
        uint32_t tAh = base + (buf * 4 + 0) * TILE_B;
        uint32_t tAl = base + (buf * 4 + 1) * TILE_B;
        uint32_t tBh = base + (buf * 4 + 2) * TILE_B;
        uint32_t tBl = base + (buf * 4 + 3) * TILE_B;
        float4 f0 = xf[0], f1 = xf[1];
        __nv_bfloat162 h01 = __floats2bfloat162_rn(f0.x, f0.y);
        __nv_bfloat162 h23 = __floats2bfloat162_rn(f0.z, f0.w);
        __nv_bfloat162 h45 = __floats2bfloat162_rn(f1.x, f1.y);
        __nv_bfloat162 h67 = __floats2bfloat162_rn(f1.z, f1.w);
        float2 r01 = __bfloat1622float2(h01), r23 = __bfloat1622float2(h23);
        float2 r45 = __bfloat1622float2(h45), r67 = __bfloat1622float2(h67);
        sts128(tAh + aoff, make_uint4(b2u(h01), b2u(h23), b2u(h45), b2u(h67)));
        sts128(tAl + aoff, make_uint4(
            b2u(__floats2bfloat162_rn(f0.x - r01.x, f0.y - r01.y)),
            b2u(__floats2bfloat162_rn(f0.z - r23.x, f0.w - r23.y)),
            b2u(__floats2bfloat162_rn(f1.x - r45.x, f1.y - r45.y)),
            b2u(__floats2bfloat162_rn(f1.z - r67.x, f1.w - r67.y))));
        sts128(tBh + aoff, whv);
        sts128(tBl + aoff, wlv);
    };

    prefetch(0);
    cvstore(0);
    __syncthreads();

    for (int s = 0; s < DIN / 32; s++) {          // 16 stages
        if (s + 1 < DIN / 32) prefetch(s + 1);

        // fused copy chunk (independent; overlaps MMA waits)
        {
            int i = blockIdx.x * 16384 + s * 1024 + tid * 2;
#pragma unroll
            for (int r = 0; r < 2; r++)
                if (i + r < NN * DIN / 4) cdst[i + r] = csrc[i + r];
        }

        int buf = s & 1;
        uint32_t tAh = base + (buf * 4 + 0) * TILE_B;
        uint32_t tAl = base + (buf * 4 + 1) * TILE_B;
        uint32_t tBh = base + (buf * 4 + 2) * TILE_B;
        uint32_t tBl = base + (buf * 4 + 3) * TILE_B;
#pragma unroll
        for (int ks = 0; ks < 32; ks += 16) {
            unsigned Ah[2][4], Al[2][4];
#pragma unroll
            for (int mt = 0; mt < 2; mt++) {
                uint32_t off = ((a_r + mt * 16) * LDP + ks + a_c) * 2;
                ldsm4(Ah[mt], tAh + off);
                ldsm4(Al[mt], tAl + off);
            }
#pragma unroll
            for (int ntp = 0; ntp < 2; ntp++) {
                unsigned Bh[4], Bl[4];
                uint32_t off = ((b_r + ntp * 16) * LDP + ks + b_c) * 2;
                ldsm4(Bh, tBh + off);
                ldsm4(Bl, tBl + off);
#pragma unroll
                for (int mt = 0; mt < 2; mt++) {
                    mma16816(acc[mt][ntp * 2],     Ah[mt], &Bh[0]);
                    mma16816(acc[mt][ntp * 2],     Ah[mt], &Bl[0]);
                    mma16816(acc[mt][ntp * 2],     Al[mt], &Bh[0]);
                    mma16816(acc[mt][ntp * 2 + 1], Ah[mt], &Bh[2]);
                    mma16816(acc[mt][ntp * 2 + 1], Ah[mt], &Bl[2]);
                    mma16816(acc[mt][ntp * 2 + 1], Al[mt], &Bh[2]);
                }
            }
        }

        if (s + 1 < DIN / 32) {
            cvstore((s + 1) & 1);
            __syncthreads();
        }
    }

    // epilogue: bias + relu; write g_hb[0] (iterate) and g_hb[2] (h0), fp16
    int group = lane >> 2, tig = lane & 3;
#pragma unroll
    for (int mt = 0; mt < 2; mt++) {
#pragma unroll
        for (int nt = 0; nt < 4; nt++) {
            int col = warp_n * 32 + nt * 8 + 2 * tig;
            float bx = B1[col], by = B1[col + 1];
#pragma unroll
            for (int h = 0; h < 2; h++) {
                int row = brow + warp_m * 32 + mt * 16 + group + h * 8;
                if (row >= NN) continue;
                float v0 = fmaxf(acc[mt][nt][h * 2]     + bx, 0.f);
                float v1 = fmaxf(acc[mt][nt][h * 2 + 1] + by, 0.f);
                __half2 hv = __floats2half2_rn(v0, v1);
                size_t off = ((size_t)row << 6) + (col >> 1);
                g_hb[0][off] = hv;
                g_hb[2][off] = hv;
            }
        }
    }
}

// ---------------- fused APPNP step -------------------------------------------
__device__ __forceinline__ void acc_edge(const __half2* __restrict__ xin,
                                         int s, float w, int lane,
                                         float& a0, float& a1, float& a2, float& a3) {
    uint2 raw = __ldg((const uint2*)(xin + ((size_t)s << 6) + (lane << 1)));
    float2 f01 = __half22float2(*reinterpret_cast<__half2*>(&raw.x));
    float2 f23 = __half22float2(*reinterpret_cast<__half2*>(&raw.y));
    a0 += w * f01.x; a1 += w * f01.y; a2 += w * f23.x; a3 += w * f23.y;
}

__global__ void __launch_bounds__(256) k_diff(int inb, int outb, int pin_i, int pout_i,
                                              float* __restrict__ emb_out, int last) {
    if (blockIdx.x < NBF2) {
        int wg   = (blockIdx.x << 3) + (threadIdx.x >> 5);
        int lane = threadIdx.x & 31;
        int n0 = wg << 3;
        int n1 = n0 + 8; if (n1 > NN) n1 = NN;
        const __half2* __restrict__ xin = g_hb[inb];
        for (int n = n0; n < n1; n++) {
            int beg = g_rowptr[n], end = g_rowptr[n + 1];
            float a0 = 0.f, a1 = 0.f, a2 = 0.f, a3 = 0.f;
            int e = beg;
            if ((e & 1) && e < end) {
                int2 cw = __ldg(&g_cw[e]);
                acc_edge(xin, cw.x, __int_as_float(cw.y), lane, a0, a1, a2, a3);
                e++;
            }
            for (; e + 8 <= end; e += 8) {
                int4 q0 = __ldg((const int4*)(g_cw + e));
                int4 q1 = __ldg((const int4*)(g_cw + e + 2));
                int4 q2 = __ldg((const int4*)(g_cw + e + 4));
                int4 q3 = __ldg((const int4*)(g_cw + e + 6));
                uint2 v[8];
                v[0] = __ldg((const uint2*)(xin + ((size_t)q0.x << 6) + (lane << 1)));
                v[1] = __ldg((const uint2*)(xin + ((size_t)q0.z << 6) + (lane << 1)));
                v[2] = __ldg((const uint2*)(xin + ((size_t)q1.x << 6) + (lane << 1)));
                v[3] = __ldg((const uint2*)(xin + ((size_t)q1.z << 6) + (lane << 1)));
                v[4] = __ldg((const uint2*)(xin + ((size_t)q2.x << 6) + (lane << 1)));
                v[5] = __ldg((const uint2*)(xin + ((size_t)q2.z << 6) + (lane << 1)));
                v[6] = __ldg((const uint2*)(xin + ((size_t)q3.x << 6) + (lane << 1)));
                v[7] = __ldg((const uint2*)(xin + ((size_t)q3.z << 6) + (lane << 1)));
                float wv[8] = {__int_as_float(q0.y), __int_as_float(q0.w),
                               __int_as_float(q1.y), __int_as_float(q1.w),
                               __int_as_float(q2.y), __int_as_float(q2.w),
                               __int_as_float(q3.y), __int_as_float(q3.w)};
#pragma unroll
                for (int i = 0; i < 8; i++) {
                    float2 f01 = __half22float2(*reinterpret_cast<__half2*>(&v[i].x));
                    float2 f23 = __half22float2(*reinterpret_cast<__half2*>(&v[i].y));
                    a0 += wv[i] * f01.x; a1 += wv[i] * f01.y;
                    a2 += wv[i] * f23.x; a3 += wv[i] * f23.y;
                }
            }
            for (; e + 2 <= end; e += 2) {
                int4 q = __ldg((const int4*)(g_cw + e));
                acc_edge(xin, q.x, __int_as_float(q.y), lane, a0, a1, a2, a3);
                acc_edge(xin, q.z, __int_as_float(q.w), lane, a0, a1, a2, a3);
            }
            if (e < end) {
                int2 cw = __ldg(&g_cw[e]);
                acc_edge(xin, cw.x, __int_as_float(cw.y), lane, a0, a1, a2, a3);
            }
            uint2 hraw = __ldg((const uint2*)(g_hb[2] + ((size_t)n << 6) + (lane << 1)));
            float2 h01 = __half22float2(*reinterpret_cast<__half2*>(&hraw.x));
            float2 h23 = __half22float2(*reinterpret_cast<__half2*>(&hraw.y));
            float4 o = make_float4(OMA * a0 + AL * h01.x, OMA * a1 + AL * h01.y,
                                   OMA * a2 + AL * h23.x, OMA * a3 + AL * h23.y);
            if (last) {
                *(float4*)(emb_out + ((size_t)n << 7) + (lane << 2)) = o;
            } else {
                uint2 hp;
                hp.x = h2u(__floats2half2_rn(o.x, o.y));
                hp.y = h2u(__floats2half2_rn(o.z, o.w));
                *(uint2*)(&g_hb[outb][((size_t)n << 6) + (lane << 1)]) = hp;
            }
        }
    } else {
        int v = (blockIdx.x - NBF2) * 256 + threadIdx.x;
        if (v >= NN) return;
        const float* __restrict__ pin = g_p[pin_i];
        float acc = 0.f;
        int beg = g_rowptr[v], end = g_rowptr[v + 1];
        int e = beg;
        if ((e & 1) && e < end) {
            int2 cw = __ldg(&g_cw[e]);
            acc += __int_as_float(cw.y) * __ldg(&pin[cw.x]);
            e++;
        }
        for (; e + 4 <= end; e += 4) {
            int4 q0 = __ldg((const int4*)(g_cw + e));
            int4 q1 = __ldg((const int4*)(g_cw + e + 2));
            float p0 = __ldg(&pin[q0.x]), p1 = __ldg(&pin[q0.z]);
            float p2 = __ldg(&pin[q1.x]), p3 = __ldg(&pin[q1.z]);
            acc += __int_as_float(q0.y) * p0 + __int_as_float(q0.w) * p1
                 + __int_as_float(q1.y) * p2 + __int_as_float(q1.w) * p3;
        }
        for (; e < end; e++) {
            int2 cw = __ldg(&g_cw[e]);
            acc += __int_as_float(cw.y) * __ldg(&pin[cw.x]);
        }
        g_p[pout_i][v] = OMA * acc + AL;
    }
}

// ---------------- GEMM2: out = emb1 @ W2^T + p * b2^T ----------------
__global__ void __launch_bounds__(256) k_gemm2(const float* __restrict__ EMB,
                                               const float* __restrict__ W2,
                                               const float* __restrict__ B2,
                                               float* __restrict__ out) {
    __shared__ float wst[DH][DC + 4];
    __shared__ float xs[16][DH];
    int tid = threadIdx.x;
#pragma unroll
    for (int i = 0; i < 8; i++) {
        int slot = tid + i * 256;
        int j = slot >> 5, k4 = slot & 31;
        float4 v = *(const float4*)(W2 + (size_t)j * DH + k4 * 4);
        wst[k4 * 4 + 0][j] = v.x; wst[k4 * 4 + 1][j] = v.y;
        wst[k4 * 4 + 2][j] = v.z; wst[k4 * 4 + 3][j] = v.w;
    }
    int n0 = blockIdx.x * 16;
#pragma unroll
    for (int i = 0; i < 2; i++) {
        int slot = tid + i * 256;
        int r = slot >> 5, k4 = slot & 31;
        int gn = n0 + r;
        float4 v = (gn < NN) ? *(const float4*)(EMB + (size_t)gn * DH + k4 * 4)
                             : make_float4(0.f, 0.f, 0.f, 0.f);
        *(float4*)&xs[r][k4 * 4] = v;
    }
    __syncthreads();
    int nl = tid >> 4, jg = tid & 15;
    float a0 = 0.f, a1 = 0.f, a2 = 0.f, a3 = 0.f;
#pragma unroll
    for (int k = 0; k < DH; k++) {
        float xv = xs[nl][k];
        float4 wv = *(const float4*)&wst[k][jg * 4];
        a0 += xv * wv.x; a1 += xv * wv.y; a2 += xv * wv.z; a3 += xv * wv.w;
    }
    int gn = n0 + nl;
    if (gn < NN) {
        float pv = g_p[0][gn];
        float4 bv = *(const float4*)(B2 + jg * 4);
        float4 o = make_float4(a0 + pv * bv.x, a1 + pv * bv.y,
                               a2 + pv * bv.z, a3 + pv * bv.w);
        *(float4*)(out + (size_t)gn * DC + jg * 4) = o;
    }
}

// ---------------- host launcher ----------------
extern "C" void kernel_launch(void* const* d_in, const int* in_sizes, int n_in,
                              void* d_out, int out_size) {
    const float* X  = (const float*)d_in[0];
    const int*   EI = (const int*)  d_in[1];
    const float* W1 = (const float*)d_in[2];
    const float* B1 = (const float*)d_in[3];
    const float* W2 = (const float*)d_in[4];
    const float* B2 = (const float*)d_in[5];
    float* out = (float*)d_out;
    float* emb_out = out + (size_t)NN * DIN;
    float* cls_out = out + (size_t)NN * (DIN + DH);

    cudaFuncSetAttribute(k_gemm1, cudaFuncAttributeMaxDynamicSharedMemorySize, G1_SMEM);

    // ordered so the profiler slot (4th launch) = k_gemm1
    k_wsplit<<<256 + NSB, 256>>>(W1);              // W split + per-node init
    k_deg   <<<(EE + 255) / 256, 256>>>(EI);
    k_scan1 <<<NSB, 256>>>();
    k_gemm1 <<<G1B, 512, G1_SMEM>>>(X, B1, out);   // gemm + fused x passthrough
    k_scan2 <<<1, 256>>>();
    k_scan3 <<<NSB, 256>>>();
    k_fill  <<<(ET + 255) / 256, 256>>>(EI);

    // fused APPNP: fp16 features (hb0 = h1, ping-pong 0<->1, h0 in hb2) + p
    {
        int pin = 0, pob = 1;
        for (int it = 0; it < KIT; it++) {
            int last = (it == KIT - 1);
            k_diff<<<NBF2 + NBP, 256>>>(it & 1, (it + 1) & 1, pin, pob, emb_out, last);
            int t = pin; pin = pob; pob = t;
        }
    }

    k_gemm2<<<(NN + 15) / 16, 256>>>(emb_out, W2, B2, cls_out);
}